// round 4
// baseline (speedup 1.0000x reference)
#include <cuda_runtime.h>
#include <math.h>
#include <stdint.h>

#define BATCH 4
#define SEQ   4096
#define DIM   1024
#define HEADS 16
#define DH    64
#define CHUNK 128
#define NCHUNK 32
#define BH    (BATCH*HEADS)
#define FEAT_SCALE 0.35355339059327373f  // 64^-0.25

// ---------------- scratch (device globals; no allocation allowed) ----------------
__device__ float g_qkv  [BATCH*SEQ*3*DIM];
__device__ float g_xr   [BATCH*SEQ*DIM];
__device__ float g_wqkvr[DIM*3*DIM];
__device__ float g_woutr[DIM*DIM];
__device__ float g_qf  [BH*SEQ*DH];
__device__ float g_kf  [BH*SEQ*DH];
__device__ float g_v   [BH*SEQ*DH];
__device__ float g_attn[BATCH*SEQ*DIM];
__device__ float g_kvch[BH*NCHUNK*DH*DH];
__device__ float g_ksch[BH*NCHUNK*DH];

// ---------------- helpers ----------------
__device__ __forceinline__ float tf32r(float x) {
    uint32_t u;
    asm("cvt.rna.tf32.f32 %0, %1;" : "=r"(u) : "f"(x));
    return __uint_as_float(u);
}
__device__ __forceinline__ void cpasync16(void* dst, const void* src) {
    unsigned d = (unsigned)__cvta_generic_to_shared(dst);
    asm volatile("cp.async.ca.shared.global [%0], [%1], 16;" :: "r"(d), "l"(src));
}
#define CP_COMMIT()  asm volatile("cp.async.commit_group;")
#define CP_WAIT1()   asm volatile("cp.async.wait_group 1;")

// accurate sincos (immune to --use_fast_math)
__device__ __forceinline__ void rope_sincos(float ang, float& s, float& c) {
    double a  = (double)ang;
    double qd = floor(a * 0.63661977236758134 + 0.5);
    double r  = a - qd * 1.5707963267948966;
    float rf = (float)r;
    int qi = ((int)qd) & 3;
    float r2 = rf * rf;
    float sp = rf * (1.0f + r2 * (-1.6666667e-1f + r2 * (8.3333337e-3f
              + r2 * (-1.9841270e-4f + r2 * 2.7557319e-6f))));
    float cp = 1.0f + r2 * (-0.5f + r2 * (4.1666668e-2f
              + r2 * (-1.3888889e-3f + r2 * 2.4801587e-5f)));
    switch (qi) {
        case 0:  s =  sp; c =  cp; break;
        case 1:  s =  cp; c = -sp; break;
        case 2:  s = -sp; c = -cp; break;
        default: s = -cp; c =  sp; break;
    }
}

// ---------------- tf32 rounding pre-pass ----------------
__global__ void round_tf32_kernel(const float4* __restrict__ in, float4* __restrict__ out, int n4) {
    int i = blockIdx.x * blockDim.x + threadIdx.x;
    if (i < n4) {
        float4 v = in[i];
        v.x = tf32r(v.x); v.y = tf32r(v.y); v.z = tf32r(v.z); v.w = tf32r(v.w);
        out[i] = v;
    }
}

// ---------------- tf32 tensor-core GEMM ----------------
// Block 128x128, BK=32, 3-stage cp.async pipeline, 512 threads (16 warps 4x4),
// warp tile 32x32 -> 4 warps per SMSP keep the tensor pipe fed.
__global__ __launch_bounds__(512) void gemm_tf32(
        const float* __restrict__ A, const float* __restrict__ B,
        float* __restrict__ C, int M, int Nn, int K) {
    extern __shared__ float sm[];
    const int AS_F = 128 * 36;      // 4608
    const int BS_F = 32 * 136;      // 4352
    const int BUF_F = AS_F + BS_F;  // 8960 floats per stage

    const int tid = threadIdx.x;
    const int bx = blockIdx.x, by = blockIdx.y;
    const int warp = tid >> 5, lane = tid & 31;
    const int gid = lane >> 2, tig = lane & 3;
    const int warpM = warp & 3, warpN = warp >> 2;
    const int mBase = warpM * 32;
    const int nBase = warpN * 32;

    const float* Ab = A + (size_t)(by * 128) * K;
    const float* Bb = B + (size_t)(bx * 128);

    float acc[2][4][4];
#pragma unroll
    for (int mi = 0; mi < 2; mi++)
#pragma unroll
        for (int nj = 0; nj < 4; nj++)
#pragma unroll
            for (int r = 0; r < 4; r++) acc[mi][nj][r] = 0.0f;

    const int KT = K >> 5;

    auto load_tile = [&](int kt, float* buf) {
        float* As = buf;
        float* Bs = buf + AS_F;
        int k0 = kt * 32;
#pragma unroll
        for (int i = 0; i < 2; i++) {
            int lin = i * 512 + tid;
            int m = lin >> 3;
            int kq = (lin & 7) * 4;
            cpasync16(&As[m * 36 + kq], Ab + (size_t)m * K + k0 + kq);
        }
#pragma unroll
        for (int i = 0; i < 2; i++) {
            int lin = i * 512 + tid;
            int k = lin >> 5;
            int nq = (lin & 31) * 4;
            cpasync16(&Bs[k * 136 + nq], Bb + (size_t)(k0 + k) * Nn + nq);
        }
    };

    // prologue: stages 0 and 1
    load_tile(0, sm);
    CP_COMMIT();
    load_tile(1, sm + BUF_F);
    CP_COMMIT();

    uint32_t af[2][2][4];
    uint32_t bf[2][4][2];

    for (int kt = 0; kt < KT; kt++) {
        CP_WAIT1();
        __syncthreads();

        if (kt + 2 < KT) load_tile(kt + 2, sm + ((kt + 2) % 3) * BUF_F);
        CP_COMMIT();

        const uint32_t* Au = (const uint32_t*)(sm + (kt % 3) * BUF_F);
        const uint32_t* Bu = (const uint32_t*)(sm + (kt % 3) * BUF_F + AS_F);

        // preload fragments of slice 0
#pragma unroll
        for (int nj = 0; nj < 4; nj++) {
            int n = nBase + nj * 8 + gid;
            bf[0][nj][0] = Bu[tig * 136 + n];
            bf[0][nj][1] = Bu[(tig + 4) * 136 + n];
        }
#pragma unroll
        for (int mi = 0; mi < 2; mi++) {
            int m = mBase + mi * 16 + gid;
            af[0][mi][0] = Au[m * 36 + tig];
            af[0][mi][1] = Au[(m + 8) * 36 + tig];
            af[0][mi][2] = Au[m * 36 + tig + 4];
            af[0][mi][3] = Au[(m + 8) * 36 + tig + 4];
        }

#pragma unroll
        for (int s = 0; s < 4; s++) {
            int cur = s & 1, nxt = cur ^ 1;
            if (s < 3) {
                int kk = (s + 1) * 8;
#pragma unroll
                for (int nj = 0; nj < 4; nj++) {
                    int n = nBase + nj * 8 + gid;
                    bf[nxt][nj][0] = Bu[(kk + tig) * 136 + n];
                    bf[nxt][nj][1] = Bu[(kk + tig + 4) * 136 + n];
                }
#pragma unroll
                for (int mi = 0; mi < 2; mi++) {
                    int m = mBase + mi * 16 + gid;
                    af[nxt][mi][0] = Au[m * 36 + kk + tig];
                    af[nxt][mi][1] = Au[(m + 8) * 36 + kk + tig];
                    af[nxt][mi][2] = Au[m * 36 + kk + tig + 4];
                    af[nxt][mi][3] = Au[(m + 8) * 36 + kk + tig + 4];
                }
            }
#pragma unroll
            for (int mi = 0; mi < 2; mi++)
#pragma unroll
                for (int nj = 0; nj < 4; nj++) {
                    asm volatile(
                        "mma.sync.aligned.m16n8k8.row.col.f32.tf32.tf32.f32 "
                        "{%0,%1,%2,%3}, {%4,%5,%6,%7}, {%8,%9}, {%0,%1,%2,%3};"
                        : "+f"(acc[mi][nj][0]), "+f"(acc[mi][nj][1]),
                          "+f"(acc[mi][nj][2]), "+f"(acc[mi][nj][3])
                        : "r"(af[cur][mi][0]), "r"(af[cur][mi][1]),
                          "r"(af[cur][mi][2]), "r"(af[cur][mi][3]),
                          "r"(bf[cur][nj][0]), "r"(bf[cur][nj][1]));
                }
        }
        __syncthreads();
    }

    // epilogue
#pragma unroll
    for (int mi = 0; mi < 2; mi++) {
        int row = by * 128 + mBase + mi * 16 + gid;
#pragma unroll
        for (int nj = 0; nj < 4; nj++) {
            int col = bx * 128 + nBase + nj * 8 + tig * 2;
            *(float2*)(C + (size_t)row * Nn + col)       = make_float2(acc[mi][nj][0], acc[mi][nj][1]);
            *(float2*)(C + (size_t)(row + 8) * Nn + col) = make_float2(acc[mi][nj][2], acc[mi][nj][3]);
        }
    }
}

// ---------------- featurize: RoPE + elu(x*s)+1, transpose to [bh][n][64] ----------------
__global__ void featurize_kernel(const float* __restrict__ qkv,
                                 float* __restrict__ qf, float* __restrict__ kf,
                                 float* __restrict__ v) {
    int idx = blockIdx.x * blockDim.x + threadIdx.x;
    int d = idx & 31;
    int h = (idx >> 5) & 15;
    int n = (idx >> 9) & 4095;
    int b = idx >> 21;

    size_t base = ((size_t)(b * SEQ + n)) * (3 * DIM);
    int col = h * 64 + d;
    float q1 = qkv[base + col],            q2 = qkv[base + col + 32];
    float k1 = qkv[base + DIM + col],      k2 = qkv[base + DIM + col + 32];
    float v1 = qkv[base + 2 * DIM + col],  v2 = qkv[base + 2 * DIM + col + 32];

    float inv_f = (float)exp(-(double)d * (9.210340371976184 / 32.0));
    float ang = (float)n * inv_f;
    float s, c;
    rope_sincos(ang, s, c);

    float qr1 = q1 * c - q2 * s, qr2 = q1 * s + q2 * c;
    float kr1 = k1 * c - k2 * s, kr2 = k1 * s + k2 * c;

    float yq1 = qr1 * FEAT_SCALE, yq2 = qr2 * FEAT_SCALE;
    float yk1 = kr1 * FEAT_SCALE, yk2 = kr2 * FEAT_SCALE;
    float fq1 = (yq1 > 0.0f) ? yq1 + 1.0f : expf(yq1);
    float fq2 = (yq2 > 0.0f) ? yq2 + 1.0f : expf(yq2);
    float fk1 = (yk1 > 0.0f) ? yk1 + 1.0f : expf(yk1);
    float fk2 = (yk2 > 0.0f) ? yk2 + 1.0f : expf(yk2);

    size_t obase = (((size_t)(b * HEADS + h)) * SEQ + n) * DH + d;
    qf[obase] = fq1; qf[obase + 32] = fq2;
    kf[obase] = fk1; kf[obase + 32] = fk2;
    v [obase] = v1;  v [obase + 32] = v2;
}

// ---------------- pass A: per-chunk K^T V (64x64) and sum(k) ----------------
__global__ void chunk_sums_kernel(const float* __restrict__ kf, const float* __restrict__ v,
                                  float* __restrict__ kvch, float* __restrict__ ksch) {
    extern __shared__ float sm[];
    float* Ks = sm;
    float* Vs = sm + 8192;

    int blk = blockIdx.x;
    int c  = blk % NCHUNK;
    int bh = blk / NCHUNK;
    int tid = threadIdx.x;

    size_t gbase = (((size_t)bh) * SEQ + (size_t)c * CHUNK) * DH;
    for (int i = tid; i < 2048; i += 256) {
        ((float4*)Ks)[i] = ((const float4*)(kf + gbase))[i];
        ((float4*)Vs)[i] = ((const float4*)(v  + gbase))[i];
    }
    __syncthreads();

    int i0 = (tid >> 4) * 4;
    int j0 = (tid & 15) * 4;
    float acc[4][4];
#pragma unroll
    for (int i = 0; i < 4; i++)
#pragma unroll
        for (int j = 0; j < 4; j++) acc[i][j] = 0.0f;

    for (int r = 0; r < CHUNK; r++) {
        float4 kv = *(const float4*)&Ks[r * 64 + i0];
        float4 vv = *(const float4*)&Vs[r * 64 + j0];
        float ka[4] = {kv.x, kv.y, kv.z, kv.w};
        float va[4] = {vv.x, vv.y, vv.z, vv.w};
#pragma unroll
        for (int i = 0; i < 4; i++)
#pragma unroll
            for (int j = 0; j < 4; j++) acc[i][j] += ka[i] * va[j];
    }

    size_t obase = ((size_t)bh * NCHUNK + c) * (DH * DH);
#pragma unroll
    for (int i = 0; i < 4; i++)
        *(float4*)&kvch[obase + (size_t)(i0 + i) * 64 + j0] =
            make_float4(acc[i][0], acc[i][1], acc[i][2], acc[i][3]);

    if (tid < 64) {
        float ssum = 0.0f;
        for (int r = 0; r < CHUNK; r++) ssum += Ks[r * 64 + tid];
        ksch[((size_t)bh * NCHUNK + c) * DH + tid] = ssum;
    }
}

// ---------------- pass B: exclusive prefix over chunks (in place) ----------------
__global__ void prefix_kernel(float* __restrict__ kvch, float* __restrict__ ksch) {
    int bh = blockIdx.x;
    for (int e = threadIdx.x; e < DH * DH; e += blockDim.x) {
        float acc = 0.0f;
        for (int c = 0; c < NCHUNK; c++) {
            float* p = &kvch[((size_t)bh * NCHUNK + c) * (DH * DH) + e];
            float t = *p; *p = acc; acc += t;
        }
    }
    for (int e = threadIdx.x; e < DH; e += blockDim.x) {
        float acc = 0.0f;
        for (int c = 0; c < NCHUNK; c++) {
            float* p = &ksch[((size_t)bh * NCHUNK + c) * DH + e];
            float t = *p; *p = acc; acc += t;
        }
    }
}

// ---------------- pass C: per-chunk output (stores attn tf32-rounded) ----------------
__global__ void chunk_out_kernel(const float* __restrict__ qf, const float* __restrict__ kf,
                                 const float* __restrict__ v, const float* __restrict__ kvch,
                                 const float* __restrict__ ksch, float* __restrict__ attn) {
    extern __shared__ float sm[];
    float* Qs   = sm;                       // 8192
    float* KsT  = Qs + 8192;                // 8448 (pitch 132)
    float* Vs   = KsT + 8448;               // 8192
    float* Ss   = Vs + 8192;                // 16384
    float* KVp  = Ss + 16384;               // 4096
    float* KSp  = KVp + 4096;               // 64
    float* den  = KSp + 64;                 // 128
    float* denp = den + 128;                // 2048

    int blk = blockIdx.x;
    int c  = blk % NCHUNK;
    int bh = blk / NCHUNK;
    int b  = bh / HEADS;
    int h  = bh % HEADS;
    int tid = threadIdx.x;

    size_t gbase = (((size_t)bh) * SEQ + (size_t)c * CHUNK) * DH;
    for (int i = tid; i < 2048; i += 256) {
        ((float4*)Qs)[i] = ((const float4*)(qf + gbase))[i];
        ((float4*)Vs)[i] = ((const float4*)(v  + gbase))[i];
        float4 kq = ((const float4*)(kf + gbase))[i];
        int r  = i >> 4;
        int c4 = (i & 15) * 4;
        KsT[(c4 + 0) * 132 + r] = kq.x;
        KsT[(c4 + 1) * 132 + r] = kq.y;
        KsT[(c4 + 2) * 132 + r] = kq.z;
        KsT[(c4 + 3) * 132 + r] = kq.w;
    }
    {
        size_t kvbase = ((size_t)bh * NCHUNK + c) * (DH * DH);
        for (int i = tid; i < 1024; i += 256)
            ((float4*)KVp)[i] = ((const float4*)(kvch + kvbase))[i];
        if (tid < 64)
            KSp[tid] = ksch[((size_t)bh * NCHUNK + c) * DH + tid];
    }
    __syncthreads();

    int ti = tid >> 4, tj = tid & 15;
    int t0 = ti * 8, s0 = tj * 8;
    {
        float acc[8][8];
#pragma unroll
        for (int i = 0; i < 8; i++)
#pragma unroll
            for (int j = 0; j < 8; j++) acc[i][j] = 0.0f;

        for (int dd = 0; dd < DH; dd++) {
            float ra[8], rb[8];
#pragma unroll
            for (int i = 0; i < 8; i++) ra[i] = Qs[(t0 + i) * 64 + dd];
            *(float4*)&rb[0] = *(const float4*)&KsT[dd * 132 + s0];
            *(float4*)&rb[4] = *(const float4*)&KsT[dd * 132 + s0 + 4];
#pragma unroll
            for (int i = 0; i < 8; i++)
#pragma unroll
                for (int j = 0; j < 8; j++) acc[i][j] += ra[i] * rb[j];
        }
#pragma unroll
        for (int i = 0; i < 8; i++) {
            float rsum = 0.0f;
#pragma unroll
            for (int j = 0; j < 8; j++) {
                float val = (s0 + j <= t0 + i) ? acc[i][j] : 0.0f;
                acc[i][j] = val;
                rsum += val;
            }
            denp[(t0 + i) * 16 + tj] = rsum;
            *(float4*)&Ss[(t0 + i) * 128 + s0]     = make_float4(acc[i][0], acc[i][1], acc[i][2], acc[i][3]);
            *(float4*)&Ss[(t0 + i) * 128 + s0 + 4] = make_float4(acc[i][4], acc[i][5], acc[i][6], acc[i][7]);
        }
    }
    __syncthreads();

    if (tid < 128) {
        float dsum = 0.0f;
#pragma unroll
        for (int j = 0; j < 16; j++) dsum += denp[tid * 16 + j];
        for (int dd = 0; dd < DH; dd++) dsum += Qs[tid * 64 + dd] * KSp[dd];
        den[tid] = fmaxf(dsum, 1e-6f);
    }
    __syncthreads();

    {
        int m0 = tj * 4;
        float acc[8][4];
#pragma unroll
        for (int i = 0; i < 8; i++)
#pragma unroll
            for (int j = 0; j < 4; j++) acc[i][j] = 0.0f;

        for (int s = 0; s < CHUNK; s++) {
            float4 vv = *(const float4*)&Vs[s * 64 + m0];
            float va[4] = {vv.x, vv.y, vv.z, vv.w};
#pragma unroll
            for (int i = 0; i < 8; i++) {
                float sv = Ss[(t0 + i) * 128 + s];
#pragma unroll
                for (int j = 0; j < 4; j++) acc[i][j] += sv * va[j];
            }
        }
        for (int dd = 0; dd < DH; dd++) {
            float4 kv = *(const float4*)&KVp[dd * 64 + m0];
            float ka[4] = {kv.x, kv.y, kv.z, kv.w};
#pragma unroll
            for (int i = 0; i < 8; i++) {
                float qv = Qs[(t0 + i) * 64 + dd];
#pragma unroll
                for (int j = 0; j < 4; j++) acc[i][j] += qv * ka[j];
            }
        }
#pragma unroll
        for (int i = 0; i < 8; i++) {
            float inv = 1.0f / den[t0 + i];
            size_t ob = ((size_t)b * SEQ + (size_t)c * CHUNK + t0 + i) * DIM + h * 64 + m0;
            attn[ob + 0] = tf32r(acc[i][0] * inv);
            attn[ob + 1] = tf32r(acc[i][1] * inv);
            attn[ob + 2] = tf32r(acc[i][2] * inv);
            attn[ob + 3] = tf32r(acc[i][3] * inv);
        }
    }
}

// ---------------- host launch ----------------
extern "C" void kernel_launch(void* const* d_in, const int* in_sizes, int n_in,
                              void* d_out, int out_size) {
    const float* x    = (const float*)d_in[0];
    const float* wqkv = (const float*)d_in[1];
    const float* wout = (const float*)d_in[2];
    float* out = (float*)d_out;

    float *qkv, *xr, *wqkvr, *woutr, *qf, *kf, *v, *attn, *kvch, *ksch;
    cudaGetSymbolAddress((void**)&qkv,   g_qkv);
    cudaGetSymbolAddress((void**)&xr,    g_xr);
    cudaGetSymbolAddress((void**)&wqkvr, g_wqkvr);
    cudaGetSymbolAddress((void**)&woutr, g_woutr);
    cudaGetSymbolAddress((void**)&qf,    g_qf);
    cudaGetSymbolAddress((void**)&kf,    g_kf);
    cudaGetSymbolAddress((void**)&v,     g_v);
    cudaGetSymbolAddress((void**)&attn,  g_attn);
    cudaGetSymbolAddress((void**)&kvch,  g_kvch);
    cudaGetSymbolAddress((void**)&ksch,  g_ksch);

    const size_t smemG = 3 * (128 * 36 + 32 * 136) * sizeof(float);      // 107520 B
    const size_t smemA = 2 * 8192 * sizeof(float);
    const size_t smemC = (8192 + 8448 + 8192 + 16384 + 4096 + 64 + 128 + 2048) * sizeof(float);
    cudaFuncSetAttribute(gemm_tf32,         cudaFuncAttributeMaxDynamicSharedMemorySize, (int)smemG);
    cudaFuncSetAttribute(chunk_sums_kernel, cudaFuncAttributeMaxDynamicSharedMemorySize, (int)smemA);
    cudaFuncSetAttribute(chunk_out_kernel,  cudaFuncAttributeMaxDynamicSharedMemorySize, (int)smemC);

    // 0) tf32-round inputs
    {
        int n4x = (BATCH * SEQ * DIM) / 4;
        int n4w = (DIM * 3 * DIM) / 4;
        int n4o = (DIM * DIM) / 4;
        round_tf32_kernel<<<(n4x + 255) / 256, 256>>>((const float4*)x,    (float4*)xr,    n4x);
        round_tf32_kernel<<<(n4w + 255) / 256, 256>>>((const float4*)wqkv, (float4*)wqkvr, n4w);
        round_tf32_kernel<<<(n4o + 255) / 256, 256>>>((const float4*)wout, (float4*)woutr, n4o);
    }

    // 1) qkv = xr @ wqkvr  (tensor cores, tf32, 16 warps/block)
    gemm_tf32<<<dim3(3072 / 128, 16384 / 128), 512, smemG>>>(xr, wqkvr, qkv, BATCH * SEQ, 3 * DIM, DIM);
    // 2) RoPE + elu feature + transpose
    featurize_kernel<<<(BATCH * SEQ * HEADS * 32) / 256, 256>>>(qkv, qf, kf, v);
    // 3) per-chunk K^T V sums
    chunk_sums_kernel<<<BH * NCHUNK, 256, smemA>>>(kf, v, kvch, ksch);
    // 4) exclusive prefix across chunks
    prefix_kernel<<<BH, 1024>>>(kvch, ksch);
    // 5) per-chunk outputs (attn stored tf32-rounded)
    chunk_out_kernel<<<BH * NCHUNK, 256, smemC>>>(qf, kf, v, kvch, ksch, attn);
    // 6) final = attn @ woutr
    gemm_tf32<<<dim3(1024 / 128, 16384 / 128), 512, smemG>>>(attn, woutr, out, BATCH * SEQ, DIM, DIM);
}

// round 6
// speedup vs baseline: 1.3370x; 1.3370x over previous
#include <cuda_runtime.h>
#include <cuda_fp16.h>
#include <math.h>
#include <stdint.h>

#define BATCH 4
#define SEQ   4096
#define DIM   1024
#define HEADS 16
#define DH    64
#define CHUNK 128
#define NCHUNK 32
#define BH    (BATCH*HEADS)
#define FEAT_SCALE 0.35355339059327373f  // 64^-0.25

// ---------------- scratch (device globals; no allocation allowed) ----------------
__device__ float  g_qkv  [BATCH*SEQ*3*DIM];   // fp32 qkv (GEMM1 out)
__device__ __half g_xh   [BATCH*SEQ*DIM];     // fp16 x
__device__ __half g_wqkvT[3*DIM*DIM];         // [3072][1024] K-major fp16
__device__ __half g_woutT[DIM*DIM];           // [1024][1024] K-major fp16
__device__ float  g_qf  [BH*SEQ*DH];
__device__ float  g_kf  [BH*SEQ*DH];
__device__ float  g_v   [BH*SEQ*DH];
__device__ __half g_attnh[BATCH*SEQ*DIM];     // attention out, fp16
__device__ float  g_kvch[BH*NCHUNK*DH*DH];
__device__ float  g_ksch[BH*NCHUNK*DH];

// ---------------- helpers ----------------
__device__ __forceinline__ void cpasync16(void* dst, const void* src) {
    unsigned d = (unsigned)__cvta_generic_to_shared(dst);
    asm volatile("cp.async.ca.shared.global [%0], [%1], 16;" :: "r"(d), "l"(src));
}
#define CP_COMMIT()  asm volatile("cp.async.commit_group;")
#define CP_WAIT1()   asm volatile("cp.async.wait_group 1;")

// accurate sincos (immune to --use_fast_math)
__device__ __forceinline__ void rope_sincos(float ang, float& s, float& c) {
    double a  = (double)ang;
    double qd = floor(a * 0.63661977236758134 + 0.5);
    double r  = a - qd * 1.5707963267948966;
    float rf = (float)r;
    int qi = ((int)qd) & 3;
    float r2 = rf * rf;
    float sp = rf * (1.0f + r2 * (-1.6666667e-1f + r2 * (8.3333337e-3f
              + r2 * (-1.9841270e-4f + r2 * 2.7557319e-6f))));
    float cp = 1.0f + r2 * (-0.5f + r2 * (4.1666668e-2f
              + r2 * (-1.3888889e-3f + r2 * 2.4801587e-5f)));
    switch (qi) {
        case 0:  s =  sp; c =  cp; break;
        case 1:  s =  cp; c = -sp; break;
        case 2:  s = -sp; c = -cp; break;
        default: s = -cp; c =  sp; break;
    }
}

// ---------------- fp16 conversion pre-passes ----------------
__global__ void f32_to_f16_kernel(const float2* __restrict__ in, __half2* __restrict__ out, int n2) {
    int i = blockIdx.x * blockDim.x + threadIdx.x;
    if (i < n2) out[i] = __float22half2_rn(in[i]);
}

// WT[n][k] = (half)W[k][n]
__global__ void transpose_f16(const float* __restrict__ W, __half* __restrict__ WT,
                              int K, int Nn) {
    __shared__ float t[32][33];
    int n0 = blockIdx.x * 32, k0 = blockIdx.y * 32;
    int tx = threadIdx.x, ty = threadIdx.y;   // 32 x 8
#pragma unroll
    for (int i = 0; i < 32; i += 8)
        t[ty + i][tx] = W[(size_t)(k0 + ty + i) * Nn + n0 + tx];
    __syncthreads();
#pragma unroll
    for (int i = 0; i < 32; i += 8)
        WT[(size_t)(n0 + ty + i) * K + k0 + tx] = __float2half(t[tx][ty + i]);
}

// ---------------- fp16 tensor-core GEMM: C[M,Nn] = A[M,K] @ BT[Nn,K]^T ----------------
// Block 128x128, BK=32, 3-stage cp.async, 256 threads (8 warps 2x4), warp tile 64x32,
// mma.sync m16n8k16 fp16 -> fp32. Smem pitch 20 b32/row (conflict-free).
#define APITCH 20                 // b32 per A/B smem row (32 halves data + 8 pad)
#define STAGE_B 20480             // bytes per stage: A 10240 + B 10240
__global__ __launch_bounds__(256) void gemm_f16(
        const __half* __restrict__ A, const __half* __restrict__ BT,
        float* __restrict__ C, int M, int Nn, int K) {
    extern __shared__ char smc[];

    const int tid = threadIdx.x;
    const int bx = blockIdx.x, by = blockIdx.y;
    const int warp = tid >> 5, lane = tid & 31;
    const int gid = lane >> 2, tig = lane & 3;
    const int warpM = warp & 1, warpN = warp >> 1;
    const int mBase = warpM * 64;
    const int nBase = warpN * 32;

    const __half* Ab = A  + (size_t)(by * 128) * K;
    const __half* Bb = BT + (size_t)(bx * 128) * K;

    float acc[4][4][4];
#pragma unroll
    for (int mi = 0; mi < 4; mi++)
#pragma unroll
        for (int nj = 0; nj < 4; nj++)
#pragma unroll
            for (int r = 0; r < 4; r++) acc[mi][nj][r] = 0.0f;

    const int KT = K >> 5;

    auto load_tile = [&](int kt, char* buf) {
        char* As = buf;
        char* Bs = buf + 10240;
        int k0 = kt * 32;
        // 128 rows x 32 halves = 512 x 16B chunks each for A and B; 2 per thread
#pragma unroll
        for (int i = 0; i < 2; i++) {
            int c = i * 256 + tid;
            int m = c >> 2, k8 = (c & 3) * 8;
            cpasync16(As + m * 80 + k8 * 2, Ab + (size_t)m * K + k0 + k8);
        }
#pragma unroll
        for (int i = 0; i < 2; i++) {
            int c = i * 256 + tid;
            int n = c >> 2, k8 = (c & 3) * 8;
            cpasync16(Bs + n * 80 + k8 * 2, Bb + (size_t)n * K + k0 + k8);
        }
    };

    load_tile(0, smc);
    CP_COMMIT();
    load_tile(1, smc + STAGE_B);
    CP_COMMIT();

    uint32_t af[2][4][4];
    uint32_t bf[2][4][2];

    for (int kt = 0; kt < KT; kt++) {
        CP_WAIT1();
        __syncthreads();

        if (kt + 2 < KT) load_tile(kt + 2, smc + ((kt + 2) % 3) * STAGE_B);
        CP_COMMIT();

        const uint32_t* Au = (const uint32_t*)(smc + (kt % 3) * STAGE_B);
        const uint32_t* Bu = (const uint32_t*)(smc + (kt % 3) * STAGE_B + 10240);

        // preload fragments of k16-slice 0
#pragma unroll
        for (int nj = 0; nj < 4; nj++) {
            int n = nBase + nj * 8 + gid;
            bf[0][nj][0] = Bu[n * APITCH + tig];
            bf[0][nj][1] = Bu[n * APITCH + tig + 4];
        }
#pragma unroll
        for (int mi = 0; mi < 4; mi++) {
            int m = mBase + mi * 16 + gid;
            af[0][mi][0] = Au[m * APITCH + tig];
            af[0][mi][1] = Au[(m + 8) * APITCH + tig];
            af[0][mi][2] = Au[m * APITCH + tig + 4];
            af[0][mi][3] = Au[(m + 8) * APITCH + tig + 4];
        }

#pragma unroll
        for (int s = 0; s < 2; s++) {
            int cur = s & 1, nxt = cur ^ 1;
            if (s < 1) {
                const int kk = 8;   // b32 offset of slice 1 (halves 16..31)
#pragma unroll
                for (int nj = 0; nj < 4; nj++) {
                    int n = nBase + nj * 8 + gid;
                    bf[nxt][nj][0] = Bu[n * APITCH + kk + tig];
                    bf[nxt][nj][1] = Bu[n * APITCH + kk + tig + 4];
                }
#pragma unroll
                for (int mi = 0; mi < 4; mi++) {
                    int m = mBase + mi * 16 + gid;
                    af[nxt][mi][0] = Au[m * APITCH + kk + tig];
                    af[nxt][mi][1] = Au[(m + 8) * APITCH + kk + tig];
                    af[nxt][mi][2] = Au[m * APITCH + kk + tig + 4];
                    af[nxt][mi][3] = Au[(m + 8) * APITCH + kk + tig + 4];
                }
            }
#pragma unroll
            for (int mi = 0; mi < 4; mi++)
#pragma unroll
                for (int nj = 0; nj < 4; nj++) {
                    asm volatile(
                        "mma.sync.aligned.m16n8k16.row.col.f32.f16.f16.f32 "
                        "{%0,%1,%2,%3}, {%4,%5,%6,%7}, {%8,%9}, {%0,%1,%2,%3};"
                        : "+f"(acc[mi][nj][0]), "+f"(acc[mi][nj][1]),
                          "+f"(acc[mi][nj][2]), "+f"(acc[mi][nj][3])
                        : "r"(af[cur][mi][0]), "r"(af[cur][mi][1]),
                          "r"(af[cur][mi][2]), "r"(af[cur][mi][3]),
                          "r"(bf[cur][nj][0]), "r"(bf[cur][nj][1]));
                }
        }
        __syncthreads();
    }

    // epilogue
#pragma unroll
    for (int mi = 0; mi < 4; mi++) {
        int row = by * 128 + mBase + mi * 16 + gid;
#pragma unroll
        for (int nj = 0; nj < 4; nj++) {
            int col = bx * 128 + nBase + nj * 8 + tig * 2;
            *(float2*)(C + (size_t)row * Nn + col)       = make_float2(acc[mi][nj][0], acc[mi][nj][1]);
            *(float2*)(C + (size_t)(row + 8) * Nn + col) = make_float2(acc[mi][nj][2], acc[mi][nj][3]);
        }
    }
}

// ---------------- featurize: RoPE + elu(x*s)+1, transpose to [bh][n][64] ----------------
__global__ void featurize_kernel(const float* __restrict__ qkv,
                                 float* __restrict__ qf, float* __restrict__ kf,
                                 float* __restrict__ v) {
    int idx = blockIdx.x * blockDim.x + threadIdx.x;
    int d = idx & 31;
    int h = (idx >> 5) & 15;
    int n = (idx >> 9) & 4095;
    int b = idx >> 21;

    size_t base = ((size_t)(b * SEQ + n)) * (3 * DIM);
    int col = h * 64 + d;
    float q1 = qkv[base + col],            q2 = qkv[base + col + 32];
    float k1 = qkv[base + DIM + col],      k2 = qkv[base + DIM + col + 32];
    float v1 = qkv[base + 2 * DIM + col],  v2 = qkv[base + 2 * DIM + col + 32];

    float inv_f = (float)exp(-(double)d * (9.210340371976184 / 32.0));
    float ang = (float)n * inv_f;
    float s, c;
    rope_sincos(ang, s, c);

    float qr1 = q1 * c - q2 * s, qr2 = q1 * s + q2 * c;
    float kr1 = k1 * c - k2 * s, kr2 = k1 * s + k2 * c;

    float yq1 = qr1 * FEAT_SCALE, yq2 = qr2 * FEAT_SCALE;
    float yk1 = kr1 * FEAT_SCALE, yk2 = kr2 * FEAT_SCALE;
    float fq1 = (yq1 > 0.0f) ? yq1 + 1.0f : expf(yq1);
    float fq2 = (yq2 > 0.0f) ? yq2 + 1.0f : expf(yq2);
    float fk1 = (yk1 > 0.0f) ? yk1 + 1.0f : expf(yk1);
    float fk2 = (yk2 > 0.0f) ? yk2 + 1.0f : expf(yk2);

    size_t obase = (((size_t)(b * HEADS + h)) * SEQ + n) * DH + d;
    qf[obase] = fq1; qf[obase + 32] = fq2;
    kf[obase] = fk1; kf[obase + 32] = fk2;
    v [obase] = v1;  v [obase + 32] = v2;
}

// ---------------- pass A: per-chunk K^T V (64x64) and sum(k) ----------------
__global__ void chunk_sums_kernel(const float* __restrict__ kf, const float* __restrict__ v,
                                  float* __restrict__ kvch, float* __restrict__ ksch) {
    extern __shared__ float sm[];
    float* Ks = sm;
    float* Vs = sm + 8192;

    int blk = blockIdx.x;
    int c  = blk % NCHUNK;
    int bh = blk / NCHUNK;
    int tid = threadIdx.x;

    size_t gbase = (((size_t)bh) * SEQ + (size_t)c * CHUNK) * DH;
    for (int i = tid; i < 2048; i += 256) {
        ((float4*)Ks)[i] = ((const float4*)(kf + gbase))[i];
        ((float4*)Vs)[i] = ((const float4*)(v  + gbase))[i];
    }
    __syncthreads();

    int i0 = (tid >> 4) * 4;
    int j0 = (tid & 15) * 4;
    float acc[4][4];
#pragma unroll
    for (int i = 0; i < 4; i++)
#pragma unroll
        for (int j = 0; j < 4; j++) acc[i][j] = 0.0f;

    for (int r = 0; r < CHUNK; r++) {
        float4 kv = *(const float4*)&Ks[r * 64 + i0];
        float4 vv = *(const float4*)&Vs[r * 64 + j0];
        float ka[4] = {kv.x, kv.y, kv.z, kv.w};
        float va[4] = {vv.x, vv.y, vv.z, vv.w};
#pragma unroll
        for (int i = 0; i < 4; i++)
#pragma unroll
            for (int j = 0; j < 4; j++) acc[i][j] += ka[i] * va[j];
    }

    size_t obase = ((size_t)bh * NCHUNK + c) * (DH * DH);
#pragma unroll
    for (int i = 0; i < 4; i++)
        *(float4*)&kvch[obase + (size_t)(i0 + i) * 64 + j0] =
            make_float4(acc[i][0], acc[i][1], acc[i][2], acc[i][3]);

    if (tid < 64) {
        float ssum = 0.0f;
        for (int r = 0; r < CHUNK; r++) ssum += Ks[r * 64 + tid];
        ksch[((size_t)bh * NCHUNK + c) * DH + tid] = ssum;
    }
}

// ---------------- pass B: exclusive prefix over chunks (in place) ----------------
__global__ void prefix_kernel(float* __restrict__ kvch, float* __restrict__ ksch) {
    int bh = blockIdx.x;
    for (int e = threadIdx.x; e < DH * DH; e += blockDim.x) {
        float acc = 0.0f;
        for (int c = 0; c < NCHUNK; c++) {
            float* p = &kvch[((size_t)bh * NCHUNK + c) * (DH * DH) + e];
            float t = *p; *p = acc; acc += t;
        }
    }
    for (int e = threadIdx.x; e < DH; e += blockDim.x) {
        float acc = 0.0f;
        for (int c = 0; c < NCHUNK; c++) {
            float* p = &ksch[((size_t)bh * NCHUNK + c) * DH + e];
            float t = *p; *p = acc; acc += t;
        }
    }
}

// ---------------- pass C: per-chunk output (stores attn as fp16) ----------------
__global__ void chunk_out_kernel(const float* __restrict__ qf, const float* __restrict__ kf,
                                 const float* __restrict__ v, const float* __restrict__ kvch,
                                 const float* __restrict__ ksch, __half* __restrict__ attn) {
    extern __shared__ float sm[];
    float* Qs   = sm;                       // 8192
    float* KsT  = Qs + 8192;                // 8448 (pitch 132)
    float* Vs   = KsT + 8448;               // 8192
    float* Ss   = Vs + 8192;                // 16384
    float* KVp  = Ss + 16384;               // 4096
    float* KSp  = KVp + 4096;               // 64
    float* den  = KSp + 64;                 // 128
    float* denp = den + 128;                // 2048

    int blk = blockIdx.x;
    int c  = blk % NCHUNK;
    int bh = blk / NCHUNK;
    int b  = bh / HEADS;
    int h  = bh % HEADS;
    int tid = threadIdx.x;

    size_t gbase = (((size_t)bh) * SEQ + (size_t)c * CHUNK) * DH;
    for (int i = tid; i < 2048; i += 256) {
        ((float4*)Qs)[i] = ((const float4*)(qf + gbase))[i];
        ((float4*)Vs)[i] = ((const float4*)(v  + gbase))[i];
        float4 kq = ((const float4*)(kf + gbase))[i];
        int r  = i >> 4;
        int c4 = (i & 15) * 4;
        KsT[(c4 + 0) * 132 + r] = kq.x;
        KsT[(c4 + 1) * 132 + r] = kq.y;
        KsT[(c4 + 2) * 132 + r] = kq.z;
        KsT[(c4 + 3) * 132 + r] = kq.w;
    }
    {
        size_t kvbase = ((size_t)bh * NCHUNK + c) * (DH * DH);
        for (int i = tid; i < 1024; i += 256)
            ((float4*)KVp)[i] = ((const float4*)(kvch + kvbase))[i];
        if (tid < 64)
            KSp[tid] = ksch[((size_t)bh * NCHUNK + c) * DH + tid];
    }
    __syncthreads();

    int ti = tid >> 4, tj = tid & 15;
    int t0 = ti * 8, s0 = tj * 8;
    {
        float acc[8][8];
#pragma unroll
        for (int i = 0; i < 8; i++)
#pragma unroll
            for (int j = 0; j < 8; j++) acc[i][j] = 0.0f;

        for (int dd = 0; dd < DH; dd++) {
            float ra[8], rb[8];
#pragma unroll
            for (int i = 0; i < 8; i++) ra[i] = Qs[(t0 + i) * 64 + dd];
            *(float4*)&rb[0] = *(const float4*)&KsT[dd * 132 + s0];
            *(float4*)&rb[4] = *(const float4*)&KsT[dd * 132 + s0 + 4];
#pragma unroll
            for (int i = 0; i < 8; i++)
#pragma unroll
                for (int j = 0; j < 8; j++) acc[i][j] += ra[i] * rb[j];
        }
#pragma unroll
        for (int i = 0; i < 8; i++) {
            float rsum = 0.0f;
#pragma unroll
            for (int j = 0; j < 8; j++) {
                float val = (s0 + j <= t0 + i) ? acc[i][j] : 0.0f;
                acc[i][j] = val;
                rsum += val;
            }
            denp[(t0 + i) * 16 + tj] = rsum;
            *(float4*)&Ss[(t0 + i) * 128 + s0]     = make_float4(acc[i][0], acc[i][1], acc[i][2], acc[i][3]);
            *(float4*)&Ss[(t0 + i) * 128 + s0 + 4] = make_float4(acc[i][4], acc[i][5], acc[i][6], acc[i][7]);
        }
    }
    __syncthreads();

    if (tid < 128) {
        float dsum = 0.0f;
#pragma unroll
        for (int j = 0; j < 16; j++) dsum += denp[tid * 16 + j];
        for (int dd = 0; dd < DH; dd++) dsum += Qs[tid * 64 + dd] * KSp[dd];
        den[tid] = fmaxf(dsum, 1e-6f);
    }
    __syncthreads();

    {
        int m0 = tj * 4;
        float acc[8][4];
#pragma unroll
        for (int i = 0; i < 8; i++)
#pragma unroll
            for (int j = 0; j < 4; j++) acc[i][j] = 0.0f;

        for (int s = 0; s < CHUNK; s++) {
            float4 vv = *(const float4*)&Vs[s * 64 + m0];
            float va[4] = {vv.x, vv.y, vv.z, vv.w};
#pragma unroll
            for (int i = 0; i < 8; i++) {
                float sv = Ss[(t0 + i) * 128 + s];
#pragma unroll
                for (int j = 0; j < 4; j++) acc[i][j] += sv * va[j];
            }
        }
        for (int dd = 0; dd < DH; dd++) {
            float4 kv = *(const float4*)&KVp[dd * 64 + m0];
            float ka[4] = {kv.x, kv.y, kv.z, kv.w};
#pragma unroll
            for (int i = 0; i < 8; i++) {
                float qv = Qs[(t0 + i) * 64 + dd];
#pragma unroll
                for (int j = 0; j < 4; j++) acc[i][j] += qv * ka[j];
            }
        }
#pragma unroll
        for (int i = 0; i < 8; i++) {
            float inv = 1.0f / den[t0 + i];
            size_t ob = ((size_t)b * SEQ + (size_t)c * CHUNK + t0 + i) * DIM + h * 64 + m0;
            __half2* op = (__half2*)(attn + ob);
            op[0] = __floats2half2_rn(acc[i][0] * inv, acc[i][1] * inv);
            op[1] = __floats2half2_rn(acc[i][2] * inv, acc[i][3] * inv);
        }
    }
}

// ---------------- host launch ----------------
extern "C" void kernel_launch(void* const* d_in, const int* in_sizes, int n_in,
                              void* d_out, int out_size) {
    const float* x    = (const float*)d_in[0];
    const float* wqkv = (const float*)d_in[1];
    const float* wout = (const float*)d_in[2];
    float* out = (float*)d_out;

    float *qkv, *qf, *kf, *v, *kvch, *ksch;
    __half *xh, *wqkvT, *woutT, *attnh;
    cudaGetSymbolAddress((void**)&qkv,   g_qkv);
    cudaGetSymbolAddress((void**)&xh,    g_xh);
    cudaGetSymbolAddress((void**)&wqkvT, g_wqkvT);
    cudaGetSymbolAddress((void**)&woutT, g_woutT);
    cudaGetSymbolAddress((void**)&qf,    g_qf);
    cudaGetSymbolAddress((void**)&kf,    g_kf);
    cudaGetSymbolAddress((void**)&v,     g_v);
    cudaGetSymbolAddress((void**)&attnh, g_attnh);
    cudaGetSymbolAddress((void**)&kvch,  g_kvch);
    cudaGetSymbolAddress((void**)&ksch,  g_ksch);

    const size_t smemG = 3 * STAGE_B;                    // 61440 B
    const size_t smemA = 2 * 8192 * sizeof(float);
    const size_t smemC = (8192 + 8448 + 8192 + 16384 + 4096 + 64 + 128 + 2048) * sizeof(float);
    cudaFuncSetAttribute(gemm_f16,          cudaFuncAttributeMaxDynamicSharedMemorySize, (int)smemG);
    cudaFuncSetAttribute(chunk_sums_kernel, cudaFuncAttributeMaxDynamicSharedMemorySize, (int)smemA);
    cudaFuncSetAttribute(chunk_out_kernel,  cudaFuncAttributeMaxDynamicSharedMemorySize, (int)smemC);

    // 0) fp16 conversions: x -> fp16; weights -> transposed K-major fp16
    {
        int n2x = (BATCH * SEQ * DIM) / 2;
        f32_to_f16_kernel<<<(n2x + 255) / 256, 256>>>((const float2*)x, (__half2*)xh, n2x);
        transpose_f16<<<dim3(3 * DIM / 32, DIM / 32), dim3(32, 8)>>>(wqkv, wqkvT, DIM, 3 * DIM);
        transpose_f16<<<dim3(DIM / 32, DIM / 32), dim3(32, 8)>>>(wout, woutT, DIM, DIM);
    }

    // 1) qkv = xh @ wqkvT^T  (fp16 mma.sync m16n8k16)
    gemm_f16<<<dim3(3072 / 128, 16384 / 128), 256, smemG>>>(xh, wqkvT, qkv, BATCH * SEQ, 3 * DIM, DIM);
    // 2) RoPE + elu feature + transpose
    featurize_kernel<<<(BATCH * SEQ * HEADS * 32) / 256, 256>>>(qkv, qf, kf, v);
    // 3) per-chunk K^T V sums
    chunk_sums_kernel<<<BH * NCHUNK, 256, smemA>>>(kf, v, kvch, ksch);
    // 4) exclusive prefix across chunks
    prefix_kernel<<<BH, 1024>>>(kvch, ksch);
    // 5) per-chunk outputs (attn stored fp16)
    chunk_out_kernel<<<BH * NCHUNK, 256, smemC>>>(qf, kf, v, kvch, ksch, attnh);
    // 6) final = attnh @ woutT^T  (fp16 mma.sync)
    gemm_f16<<<dim3(1024 / 128, 16384 / 128), 256, smemG>>>(attnh, woutT, out, BATCH * SEQ, DIM, DIM);
}

// round 8
// speedup vs baseline: 1.7354x; 1.2980x over previous
#include <cuda_runtime.h>
#include <cuda_fp16.h>
#include <math.h>
#include <stdint.h>

#define BATCH 4
#define SEQ   4096
#define DIM   1024
#define HEADS 16
#define DH    64
#define CHUNK 128
#define NCHUNK 32
#define BH    (BATCH*HEADS)
#define FEAT_SCALE 0.35355339059327373f  // 64^-0.25

// ---------------- scratch (device globals; no allocation allowed) ----------------
__device__ float  g_qkv  [BATCH*SEQ*3*DIM];   // fp32 qkv (GEMM1 out)
__device__ __half g_xh   [BATCH*SEQ*DIM];     // fp16 x
__device__ __half g_wqkvT[3*DIM*DIM];         // K-major fp16
__device__ __half g_woutT[DIM*DIM];           // K-major fp16
__device__ __half g_qh  [BH*SEQ*DH];          // featurized q (fp16)
__device__ __half g_kh  [BH*SEQ*DH];          // featurized k (fp16)
__device__ __half g_vh  [BH*SEQ*DH];          // v (fp16)
__device__ __half g_attnh[BATCH*SEQ*DIM];     // attention out, fp16
__device__ float  g_kvch[BH*NCHUNK*DH*DH];
__device__ float  g_ksch[BH*NCHUNK*DH];

// ---------------- helpers ----------------
__device__ __forceinline__ uint32_t h2_to_u32(__half2 h) {
    __half2_raw r = *(__half2_raw*)&h;
    return (uint32_t)r.x | ((uint32_t)r.y << 16);
}
__device__ __forceinline__ __half2 u32_to_h2(uint32_t u) {
    __half2_raw r;
    r.x = (unsigned short)(u & 0xFFFF);
    r.y = (unsigned short)(u >> 16);
    return *(__half2*)&r;
}
__device__ __forceinline__ void cpasync16(void* dst, const void* src) {
    unsigned d = (unsigned)__cvta_generic_to_shared(dst);
    asm volatile("cp.async.ca.shared.global [%0], [%1], 16;" :: "r"(d), "l"(src));
}
#define CP_COMMIT()  asm volatile("cp.async.commit_group;")
#define CP_WAIT1()   asm volatile("cp.async.wait_group 1;")

#define MMA_F16(acc, a0, a1, a2, a3, b0, b1) \
    asm volatile("mma.sync.aligned.m16n8k16.row.col.f32.f16.f16.f32 " \
        "{%0,%1,%2,%3}, {%4,%5,%6,%7}, {%8,%9}, {%0,%1,%2,%3};" \
        : "+f"((acc)[0]), "+f"((acc)[1]), "+f"((acc)[2]), "+f"((acc)[3]) \
        : "r"(a0), "r"(a1), "r"(a2), "r"(a3), "r"(b0), "r"(b1))

#define LDMATRIX_X4_TRANS(r0, r1, r2, r3, addr) \
    asm volatile("ldmatrix.sync.aligned.m8n8.x4.trans.shared.b16 {%0,%1,%2,%3}, [%4];" \
        : "=r"(r0), "=r"(r1), "=r"(r2), "=r"(r3) : "r"(addr))

__device__ __forceinline__ uint32_t smem_u32p(const void* p) {
    return (uint32_t)__cvta_generic_to_shared(p);
}

// accurate sincos (immune to --use_fast_math)
__device__ __forceinline__ void rope_sincos(float ang, float& s, float& c) {
    double a  = (double)ang;
    double qd = floor(a * 0.63661977236758134 + 0.5);
    double r  = a - qd * 1.5707963267948966;
    float rf = (float)r;
    int qi = ((int)qd) & 3;
    float r2 = rf * rf;
    float sp = rf * (1.0f + r2 * (-1.6666667e-1f + r2 * (8.3333337e-3f
              + r2 * (-1.9841270e-4f + r2 * 2.7557319e-6f))));
    float cp = 1.0f + r2 * (-0.5f + r2 * (4.1666668e-2f
              + r2 * (-1.3888889e-3f + r2 * 2.4801587e-5f)));
    switch (qi) {
        case 0:  s =  sp; c =  cp; break;
        case 1:  s =  cp; c = -sp; break;
        case 2:  s = -sp; c = -cp; break;
        default: s = -cp; c =  sp; break;
    }
}

// ---------------- fp16 conversion pre-passes ----------------
__global__ void f32_to_f16_kernel(const float2* __restrict__ in, __half2* __restrict__ out, int n2) {
    int i = blockIdx.x * blockDim.x + threadIdx.x;
    if (i < n2) out[i] = __float22half2_rn(in[i]);
}

__global__ void transpose_f16(const float* __restrict__ W, __half* __restrict__ WT,
                              int K, int Nn) {
    __shared__ float t[32][33];
    int n0 = blockIdx.x * 32, k0 = blockIdx.y * 32;
    int tx = threadIdx.x, ty = threadIdx.y;
#pragma unroll
    for (int i = 0; i < 32; i += 8)
        t[ty + i][tx] = W[(size_t)(k0 + ty + i) * Nn + n0 + tx];
    __syncthreads();
#pragma unroll
    for (int i = 0; i < 32; i += 8)
        WT[(size_t)(n0 + ty + i) * K + k0 + tx] = __float2half(t[tx][ty + i]);
}

// ---------------- fp16 tensor-core GEMM (R6, unchanged) ----------------
#define APITCH 20
#define STAGE_B 20480
__global__ __launch_bounds__(256) void gemm_f16(
        const __half* __restrict__ A, const __half* __restrict__ BT,
        float* __restrict__ C, int M, int Nn, int K) {
    extern __shared__ char smc[];
    const int tid = threadIdx.x;
    const int bx = blockIdx.x, by = blockIdx.y;
    const int warp = tid >> 5, lane = tid & 31;
    const int gid = lane >> 2, tig = lane & 3;
    const int warpM = warp & 1, warpN = warp >> 1;
    const int mBase = warpM * 64;
    const int nBase = warpN * 32;

    const __half* Ab = A  + (size_t)(by * 128) * K;
    const __half* Bb = BT + (size_t)(bx * 128) * K;

    float acc[4][4][4];
#pragma unroll
    for (int mi = 0; mi < 4; mi++)
#pragma unroll
        for (int nj = 0; nj < 4; nj++)
#pragma unroll
            for (int r = 0; r < 4; r++) acc[mi][nj][r] = 0.0f;

    const int KT = K >> 5;

    auto load_tile = [&](int kt, char* buf) {
        char* As = buf;
        char* Bs = buf + 10240;
        int k0 = kt * 32;
#pragma unroll
        for (int i = 0; i < 2; i++) {
            int c = i * 256 + tid;
            int m = c >> 2, k8 = (c & 3) * 8;
            cpasync16(As + m * 80 + k8 * 2, Ab + (size_t)m * K + k0 + k8);
        }
#pragma unroll
        for (int i = 0; i < 2; i++) {
            int c = i * 256 + tid;
            int n = c >> 2, k8 = (c & 3) * 8;
            cpasync16(Bs + n * 80 + k8 * 2, Bb + (size_t)n * K + k0 + k8);
        }
    };

    load_tile(0, smc);
    CP_COMMIT();
    load_tile(1, smc + STAGE_B);
    CP_COMMIT();

    uint32_t af[2][4][4];
    uint32_t bf[2][4][2];

    for (int kt = 0; kt < KT; kt++) {
        CP_WAIT1();
        __syncthreads();
        if (kt + 2 < KT) load_tile(kt + 2, smc + ((kt + 2) % 3) * STAGE_B);
        CP_COMMIT();

        const uint32_t* Au = (const uint32_t*)(smc + (kt % 3) * STAGE_B);
        const uint32_t* Bu = (const uint32_t*)(smc + (kt % 3) * STAGE_B + 10240);

#pragma unroll
        for (int nj = 0; nj < 4; nj++) {
            int n = nBase + nj * 8 + gid;
            bf[0][nj][0] = Bu[n * APITCH + tig];
            bf[0][nj][1] = Bu[n * APITCH + tig + 4];
        }
#pragma unroll
        for (int mi = 0; mi < 4; mi++) {
            int m = mBase + mi * 16 + gid;
            af[0][mi][0] = Au[m * APITCH + tig];
            af[0][mi][1] = Au[(m + 8) * APITCH + tig];
            af[0][mi][2] = Au[m * APITCH + tig + 4];
            af[0][mi][3] = Au[(m + 8) * APITCH + tig + 4];
        }

#pragma unroll
        for (int s = 0; s < 2; s++) {
            int cur = s & 1, nxt = cur ^ 1;
            if (s < 1) {
                const int kk = 8;
#pragma unroll
                for (int nj = 0; nj < 4; nj++) {
                    int n = nBase + nj * 8 + gid;
                    bf[nxt][nj][0] = Bu[n * APITCH + kk + tig];
                    bf[nxt][nj][1] = Bu[n * APITCH + kk + tig + 4];
                }
#pragma unroll
                for (int mi = 0; mi < 4; mi++) {
                    int m = mBase + mi * 16 + gid;
                    af[nxt][mi][0] = Au[m * APITCH + kk + tig];
                    af[nxt][mi][1] = Au[(m + 8) * APITCH + kk + tig];
                    af[nxt][mi][2] = Au[m * APITCH + kk + tig + 4];
                    af[nxt][mi][3] = Au[(m + 8) * APITCH + kk + tig + 4];
                }
            }
#pragma unroll
            for (int mi = 0; mi < 4; mi++)
#pragma unroll
                for (int nj = 0; nj < 4; nj++)
                    MMA_F16(acc[mi][nj], af[cur][mi][0], af[cur][mi][1],
                            af[cur][mi][2], af[cur][mi][3],
                            bf[cur][nj][0], bf[cur][nj][1]);
        }
        __syncthreads();
    }

#pragma unroll
    for (int mi = 0; mi < 4; mi++) {
        int row = by * 128 + mBase + mi * 16 + gid;
#pragma unroll
        for (int nj = 0; nj < 4; nj++) {
            int col = bx * 128 + nBase + nj * 8 + tig * 2;
            *(float2*)(C + (size_t)row * Nn + col)       = make_float2(acc[mi][nj][0], acc[mi][nj][1]);
            *(float2*)(C + (size_t)(row + 8) * Nn + col) = make_float2(acc[mi][nj][2], acc[mi][nj][3]);
        }
    }
}

// ---------------- featurize: RoPE + elu(x*s)+1, outputs fp16 [bh][n][64] ----------------
__global__ void featurize_kernel(const float* __restrict__ qkv,
                                 __half* __restrict__ qh, __half* __restrict__ kh,
                                 __half* __restrict__ vh) {
    int idx = blockIdx.x * blockDim.x + threadIdx.x;
    int d = idx & 31;
    int h = (idx >> 5) & 15;
    int n = (idx >> 9) & 4095;
    int b = idx >> 21;

    size_t base = ((size_t)(b * SEQ + n)) * (3 * DIM);
    int col = h * 64 + d;
    float q1 = qkv[base + col],            q2 = qkv[base + col + 32];
    float k1 = qkv[base + DIM + col],      k2 = qkv[base + DIM + col + 32];
    float v1 = qkv[base + 2 * DIM + col],  v2 = qkv[base + 2 * DIM + col + 32];

    float inv_f = (float)exp(-(double)d * (9.210340371976184 / 32.0));
    float ang = (float)n * inv_f;
    float s, c;
    rope_sincos(ang, s, c);

    float qr1 = q1 * c - q2 * s, qr2 = q1 * s + q2 * c;
    float kr1 = k1 * c - k2 * s, kr2 = k1 * s + k2 * c;

    float yq1 = qr1 * FEAT_SCALE, yq2 = qr2 * FEAT_SCALE;
    float yk1 = kr1 * FEAT_SCALE, yk2 = kr2 * FEAT_SCALE;
    float fq1 = (yq1 > 0.0f) ? yq1 + 1.0f : expf(yq1);
    float fq2 = (yq2 > 0.0f) ? yq2 + 1.0f : expf(yq2);
    float fk1 = (yk1 > 0.0f) ? yk1 + 1.0f : expf(yk1);
    float fk2 = (yk2 > 0.0f) ? yk2 + 1.0f : expf(yk2);

    size_t obase = (((size_t)(b * HEADS + h)) * SEQ + n) * DH + d;
    qh[obase] = __float2half(fq1); qh[obase + 32] = __float2half(fq2);
    kh[obase] = __float2half(fk1); kh[obase + 32] = __float2half(fk2);
    vh[obase] = __float2half(v1);  vh[obase + 32] = __float2half(v2);
}

// ---------------- pass A: per-chunk K^T V (64x64) and sum(k), fp16 in / fp32 out ----------------
__global__ void chunk_sums_kernel(const __half* __restrict__ kh, const __half* __restrict__ vh,
                                  float* __restrict__ kvch, float* __restrict__ ksch) {
    extern __shared__ float sm[];
    float* Ks = sm;
    float* Vs = sm + 8192;

    int blk = blockIdx.x;
    int c  = blk % NCHUNK;
    int bh = blk / NCHUNK;
    int tid = threadIdx.x;

    size_t gbase = (((size_t)bh) * SEQ + (size_t)c * CHUNK) * DH;
    for (int i = tid; i < 1024; i += 256) {
        float4 kraw = ((const float4*)(kh + gbase))[i];
        float4 vraw = ((const float4*)(vh + gbase))[i];
        const __half2* kp = (const __half2*)&kraw;
        const __half2* vp = (const __half2*)&vraw;
#pragma unroll
        for (int j = 0; j < 4; j++) {
            float2 kf2 = __half22float2(kp[j]);
            float2 vf2 = __half22float2(vp[j]);
            Ks[i * 8 + j * 2]     = kf2.x;  Ks[i * 8 + j * 2 + 1] = kf2.y;
            Vs[i * 8 + j * 2]     = vf2.x;  Vs[i * 8 + j * 2 + 1] = vf2.y;
        }
    }
    __syncthreads();

    int i0 = (tid >> 4) * 4;
    int j0 = (tid & 15) * 4;
    float acc[4][4];
#pragma unroll
    for (int i = 0; i < 4; i++)
#pragma unroll
        for (int j = 0; j < 4; j++) acc[i][j] = 0.0f;

    for (int r = 0; r < CHUNK; r++) {
        float4 kv = *(const float4*)&Ks[r * 64 + i0];
        float4 vv = *(const float4*)&Vs[r * 64 + j0];
        float ka[4] = {kv.x, kv.y, kv.z, kv.w};
        float va[4] = {vv.x, vv.y, vv.z, vv.w};
#pragma unroll
        for (int i = 0; i < 4; i++)
#pragma unroll
            for (int j = 0; j < 4; j++) acc[i][j] += ka[i] * va[j];
    }

    size_t obase = ((size_t)bh * NCHUNK + c) * (DH * DH);
#pragma unroll
    for (int i = 0; i < 4; i++)
        *(float4*)&kvch[obase + (size_t)(i0 + i) * 64 + j0] =
            make_float4(acc[i][0], acc[i][1], acc[i][2], acc[i][3]);

    if (tid < 64) {
        float ssum = 0.0f;
        for (int r = 0; r < CHUNK; r++) ssum += Ks[r * 64 + tid];
        ksch[((size_t)bh * NCHUNK + c) * DH + tid] = ssum;
    }
}

// ---------------- pass B: exclusive prefix over chunks (in place) ----------------
__global__ void prefix_kernel(float* __restrict__ kvch, float* __restrict__ ksch) {
    int bh = blockIdx.x;
    for (int e = threadIdx.x; e < DH * DH; e += blockDim.x) {
        float acc = 0.0f;
        for (int c = 0; c < NCHUNK; c++) {
            float* p = &kvch[((size_t)bh * NCHUNK + c) * (DH * DH) + e];
            float t = *p; *p = acc; acc += t;
        }
    }
    for (int e = threadIdx.x; e < DH; e += blockDim.x) {
        float acc = 0.0f;
        for (int c = 0; c < NCHUNK; c++) {
            float* p = &ksch[((size_t)bh * NCHUNK + c) * DH + e];
            float t = *p; *p = acc; acc += t;
        }
    }
}

// ---------------- pass C: tensor-core per-chunk output ----------------
// S = QK^T (fp16 mma, fp32 acc), causal mask + rowsums in fragments,
// O = S_h V + Q KVp (fp16 mma, ldmatrix.trans for B), fp32 denominators.
#define PQ 72     // halves pitch for Q/K/V/KVp smem rows
#define PQU 36    // u32 pitch
#define PS 136    // halves pitch for S smem
#define PSU 68
__global__ __launch_bounds__(256) void chunk_out_tc(
        const __half* __restrict__ qh, const __half* __restrict__ kh,
        const __half* __restrict__ vh, const float* __restrict__ kvch,
        const float* __restrict__ ksch, __half* __restrict__ attn) {
    extern __shared__ char smem[];
    __half* Qh   = (__half*)smem;                    // 128*72*2 = 18432 B
    __half* Kh   = (__half*)(smem + 18432);          // 18432 B
    __half* Vh   = (__half*)(smem + 36864);          // 18432 B
    __half* KVph = (__half*)(smem + 55296);          // 64*72*2 = 9216 B
    __half* Sh   = (__half*)(smem + 64512);          // 128*136*2 = 34816 B
    float* rowsum = (float*)(smem + 99328);          // 512 B
    float* den    = (float*)(smem + 99840);          // 512 B
    float* KSp    = (float*)(smem + 100352);         // 256 B

    const int blk = blockIdx.x;
    const int c  = blk % NCHUNK;
    const int bh = blk / NCHUNK;
    const int b  = bh / HEADS;
    const int h  = bh % HEADS;
    const int tid = threadIdx.x;
    const int warp = tid >> 5, lane = tid & 31;
    const int gid = lane >> 2, tig = lane & 3;

    // ---- load Q/K/V chunks (fp16, [128][64] -> pitch-72 smem) ----
    size_t gbase = (((size_t)bh) * SEQ + (size_t)c * CHUNK) * DH;   // halves
    for (int i = tid; i < 1024; i += 256) {
        int row = i >> 3, c16 = (i & 7) * 16;    // byte col
        *(float4*)((char*)Qh + row * 144 + c16) = ((const float4*)(qh + gbase))[i];
        *(float4*)((char*)Kh + row * 144 + c16) = ((const float4*)(kh + gbase))[i];
        *(float4*)((char*)Vh + row * 144 + c16) = ((const float4*)(vh + gbase))[i];
    }
    // KVp fp32 -> fp16 smem [64][72]
    {
        size_t kvbase = ((size_t)bh * NCHUNK + c) * (DH * DH);
        for (int i = tid; i < 2048; i += 256) {
            int d = i >> 5, m2 = i & 31;
            float2 f = ((const float2*)(kvch + kvbase))[i];
            *(uint32_t*)((char*)KVph + d * 144 + m2 * 4) =
                h2_to_u32(__floats2half2_rn(f.x, f.y));
        }
        if (tid < 64)
            KSp[tid] = ksch[((size_t)bh * NCHUNK + c) * DH + tid];
    }
    __syncthreads();

    const uint32_t* Qu = (const uint32_t*)Qh;
    const uint32_t* Ku = (const uint32_t*)Kh;
    uint32_t* Su = (uint32_t*)Sh;
    const int r0 = warp * 16;

    // ---- stage 1: S = Q K^T, mask, rowsum, store fp16 ----
    {
        float acc1[16][4];
#pragma unroll
        for (int nt = 0; nt < 16; nt++)
#pragma unroll
            for (int r = 0; r < 4; r++) acc1[nt][r] = 0.0f;

#pragma unroll
        for (int ks = 0; ks < 4; ks++) {
            uint32_t a0 = Qu[(r0 + gid) * PQU + ks * 8 + tig];
            uint32_t a1 = Qu[(r0 + gid + 8) * PQU + ks * 8 + tig];
            uint32_t a2 = Qu[(r0 + gid) * PQU + ks * 8 + tig + 4];
            uint32_t a3 = Qu[(r0 + gid + 8) * PQU + ks * 8 + tig + 4];
#pragma unroll
            for (int nt = 0; nt < 16; nt++) {
                uint32_t b0 = Ku[(nt * 8 + gid) * PQU + ks * 8 + tig];
                uint32_t b1 = Ku[(nt * 8 + gid) * PQU + ks * 8 + tig + 4];
                MMA_F16(acc1[nt], a0, a1, a2, a3, b0, b1);
            }
        }

        int row_lo = r0 + gid, row_hi = row_lo + 8;
        float sum_lo = 0.0f, sum_hi = 0.0f;
#pragma unroll
        for (int nt = 0; nt < 16; nt++) {
            int c0 = nt * 8 + tig * 2, c1 = c0 + 1;
            float v0 = (c0 <= row_lo) ? acc1[nt][0] : 0.0f;
            float v1 = (c1 <= row_lo) ? acc1[nt][1] : 0.0f;
            float v2 = (c0 <= row_hi) ? acc1[nt][2] : 0.0f;
            float v3 = (c1 <= row_hi) ? acc1[nt][3] : 0.0f;
            sum_lo += v0 + v1;
            sum_hi += v2 + v3;
            Su[row_lo * PSU + nt * 4 + tig] = h2_to_u32(__floats2half2_rn(v0, v1));
            Su[row_hi * PSU + nt * 4 + tig] = h2_to_u32(__floats2half2_rn(v2, v3));
        }
        sum_lo += __shfl_xor_sync(0xffffffff, sum_lo, 1);
        sum_lo += __shfl_xor_sync(0xffffffff, sum_lo, 2);
        sum_hi += __shfl_xor_sync(0xffffffff, sum_hi, 1);
        sum_hi += __shfl_xor_sync(0xffffffff, sum_hi, 2);
        if (tig == 0) { rowsum[row_lo] = sum_lo; rowsum[row_hi] = sum_hi; }
    }
    __syncthreads();

    // ---- stage 2: denominators (fp32) ----
    if (tid < 128) {
        float dsum = rowsum[tid];
        const uint32_t* Qr = Qu + tid * PQU;
#pragma unroll
        for (int dd = 0; dd < 32; dd++) {
            float2 qv = __half22float2(u32_to_h2(Qr[dd]));
            dsum += qv.x * KSp[dd * 2] + qv.y * KSp[dd * 2 + 1];
        }
        den[tid] = 1.0f / fmaxf(dsum, 1e-6f);
    }
    __syncthreads();

    // ---- stage 3: O = S_h V + Q KVp ----
    {
        float acc2[8][4];
#pragma unroll
        for (int nt = 0; nt < 8; nt++)
#pragma unroll
            for (int r = 0; r < 4; r++) acc2[nt][r] = 0.0f;

        const uint32_t vbase = smem_u32p(Vh);
        const uint32_t kvbase = smem_u32p(KVph);
        const int sel = lane >> 3;
        const int srow_in = ((sel & 1) << 3) + (lane & 7);
        const int ncol_in = (sel >> 1) << 3;

        // S @ V : contraction over s (128)
#pragma unroll
        for (int ks = 0; ks < 8; ks++) {
            uint32_t a0 = Su[(r0 + gid) * PSU + ks * 8 + tig];
            uint32_t a1 = Su[(r0 + gid + 8) * PSU + ks * 8 + tig];
            uint32_t a2 = Su[(r0 + gid) * PSU + ks * 8 + tig + 4];
            uint32_t a3 = Su[(r0 + gid + 8) * PSU + ks * 8 + tig + 4];
#pragma unroll
            for (int nt2 = 0; nt2 < 4; nt2++) {
                uint32_t addr = vbase + (uint32_t)((ks * 16 + srow_in) * 144 + (nt2 * 16 + ncol_in) * 2);
                uint32_t b0, b1, b2, b3;
                LDMATRIX_X4_TRANS(b0, b1, b2, b3, addr);
                MMA_F16(acc2[nt2 * 2],     a0, a1, a2, a3, b0, b1);
                MMA_F16(acc2[nt2 * 2 + 1], a0, a1, a2, a3, b2, b3);
            }
        }
        // Q @ KVp : contraction over d (64)
#pragma unroll
        for (int ks = 0; ks < 4; ks++) {
            uint32_t a0 = Qu[(r0 + gid) * PQU + ks * 8 + tig];
            uint32_t a1 = Qu[(r0 + gid + 8) * PQU + ks * 8 + tig];
            uint32_t a2 = Qu[(r0 + gid) * PQU + ks * 8 + tig + 4];
            uint32_t a3 = Qu[(r0 + gid + 8) * PQU + ks * 8 + tig + 4];
#pragma unroll
            for (int nt2 = 0; nt2 < 4; nt2++) {
                uint32_t addr = kvbase + (uint32_t)((ks * 16 + srow_in) * 144 + (nt2 * 16 + ncol_in) * 2);
                uint32_t b0, b1, b2, b3;
                LDMATRIX_X4_TRANS(b0, b1, b2, b3, addr);
                MMA_F16(acc2[nt2 * 2],     a0, a1, a2, a3, b0, b1);
                MMA_F16(acc2[nt2 * 2 + 1], a0, a1, a2, a3, b2, b3);
            }
        }

        // epilogue: divide by denom, store fp16
        int row_lo = r0 + gid, row_hi = row_lo + 8;
        float inv_lo = den[row_lo], inv_hi = den[row_hi];
        size_t obL = ((size_t)b * SEQ + (size_t)c * CHUNK + row_lo) * DIM + h * 64;
        size_t obH = obL + (size_t)8 * DIM;
#pragma unroll
        for (int nt = 0; nt < 8; nt++) {
            int c0 = nt * 8 + tig * 2;
            *(__half2*)(attn + obL + c0) = __floats2half2_rn(acc2[nt][0] * inv_lo, acc2[nt][1] * inv_lo);
            *(__half2*)(attn + obH + c0) = __floats2half2_rn(acc2[nt][2] * inv_hi, acc2[nt][3] * inv_hi);
        }
    }
}

// ---------------- host launch ----------------
extern "C" void kernel_launch(void* const* d_in, const int* in_sizes, int n_in,
                              void* d_out, int out_size) {
    const float* x    = (const float*)d_in[0];
    const float* wqkv = (const float*)d_in[1];
    const float* wout = (const float*)d_in[2];
    float* out = (float*)d_out;

    float *qkv, *kvch, *ksch;
    __half *xh, *wqkvT, *woutT, *qh, *kh, *vh, *attnh;
    cudaGetSymbolAddress((void**)&qkv,   g_qkv);
    cudaGetSymbolAddress((void**)&xh,    g_xh);
    cudaGetSymbolAddress((void**)&wqkvT, g_wqkvT);
    cudaGetSymbolAddress((void**)&woutT, g_woutT);
    cudaGetSymbolAddress((void**)&qh,    g_qh);
    cudaGetSymbolAddress((void**)&kh,    g_kh);
    cudaGetSymbolAddress((void**)&vh,    g_vh);
    cudaGetSymbolAddress((void**)&attnh, g_attnh);
    cudaGetSymbolAddress((void**)&kvch,  g_kvch);
    cudaGetSymbolAddress((void**)&ksch,  g_ksch);

    const size_t smemG = 3 * STAGE_B;            // 61440 B
    const size_t smemA = 2 * 8192 * sizeof(float);
    const size_t smemC = 100608;
    cudaFuncSetAttribute(gemm_f16,          cudaFuncAttributeMaxDynamicSharedMemorySize, (int)smemG);
    cudaFuncSetAttribute(chunk_sums_kernel, cudaFuncAttributeMaxDynamicSharedMemorySize, (int)smemA);
    cudaFuncSetAttribute(chunk_out_tc,      cudaFuncAttributeMaxDynamicSharedMemorySize, (int)smemC);

    // 0) fp16 conversions
    {
        int n2x = (BATCH * SEQ * DIM) / 2;
        f32_to_f16_kernel<<<(n2x + 255) / 256, 256>>>((const float2*)x, (__half2*)xh, n2x);
        transpose_f16<<<dim3(3 * DIM / 32, DIM / 32), dim3(32, 8)>>>(wqkv, wqkvT, DIM, 3 * DIM);
        transpose_f16<<<dim3(DIM / 32, DIM / 32), dim3(32, 8)>>>(wout, woutT, DIM, DIM);
    }

    // 1) qkv = xh @ wqkvT^T
    gemm_f16<<<dim3(3072 / 128, 16384 / 128), 256, smemG>>>(xh, wqkvT, qkv, BATCH * SEQ, 3 * DIM, DIM);
    // 2) RoPE + elu feature -> fp16 [bh][n][64]
    featurize_kernel<<<(BATCH * SEQ * HEADS * 32) / 256, 256>>>(qkv, qh, kh, vh);
    // 3) per-chunk K^T V sums (fp32 out)
    chunk_sums_kernel<<<BH * NCHUNK, 256, smemA>>>(kh, vh, kvch, ksch);
    // 4) exclusive prefix across chunks
    prefix_kernel<<<BH, 1024>>>(kvch, ksch);
    // 5) per-chunk outputs via tensor cores
    chunk_out_tc<<<BH * NCHUNK, 256, smemC>>>(qh, kh, vh, kvch, ksch, attnh);
    // 6) final = attnh @ woutT^T
    gemm_f16<<<dim3(1024 / 128, 16384 / 128), 256, smemG>>>(attnh, woutT, out, BATCH * SEQ, DIM, DIM);
}

// round 9
// speedup vs baseline: 1.7754x; 1.0230x over previous
#include <cuda_runtime.h>
#include <cuda_fp16.h>
#include <math.h>
#include <stdint.h>

#define BATCH 4
#define SEQ   4096
#define DIM   1024
#define HEADS 16
#define DH    64
#define CHUNK 128
#define NCHUNK 32
#define BH    (BATCH*HEADS)
#define FEAT_SCALE 0.35355339059327373f  // 64^-0.25

// ---------------- scratch (device globals; no allocation allowed) ----------------
__device__ float  g_qkv  [BATCH*SEQ*3*DIM];   // fp32 qkv (GEMM1 out)
__device__ __half g_xh   [BATCH*SEQ*DIM];     // fp16 x
__device__ __half g_wqkvT[3*DIM*DIM];         // K-major fp16
__device__ __half g_woutT[DIM*DIM];           // K-major fp16
__device__ __half g_qh  [BH*SEQ*DH];          // featurized q (fp16)
__device__ __half g_kh  [BH*SEQ*DH];          // featurized k (fp16)
__device__ __half g_vh  [BH*SEQ*DH];          // v (fp16)
__device__ __half g_attnh[BATCH*SEQ*DIM];     // attention out, fp16
__device__ float  g_kvch[BH*NCHUNK*DH*DH];
__device__ float  g_ksch[BH*NCHUNK*DH];

// ---------------- helpers ----------------
__device__ __forceinline__ uint32_t h2_to_u32(__half2 h) {
    __half2_raw r = *(__half2_raw*)&h;
    return (uint32_t)r.x | ((uint32_t)r.y << 16);
}
__device__ __forceinline__ __half2 u32_to_h2(uint32_t u) {
    __half2_raw r;
    r.x = (unsigned short)(u & 0xFFFF);
    r.y = (unsigned short)(u >> 16);
    return *(__half2*)&r;
}
__device__ __forceinline__ void cpasync16(void* dst, const void* src) {
    unsigned d = (unsigned)__cvta_generic_to_shared(dst);
    asm volatile("cp.async.ca.shared.global [%0], [%1], 16;" :: "r"(d), "l"(src));
}
#define CP_COMMIT()  asm volatile("cp.async.commit_group;")
#define CP_WAIT1()   asm volatile("cp.async.wait_group 1;")

#define MMA_F16(acc, a0, a1, a2, a3, b0, b1) \
    asm volatile("mma.sync.aligned.m16n8k16.row.col.f32.f16.f16.f32 " \
        "{%0,%1,%2,%3}, {%4,%5,%6,%7}, {%8,%9}, {%0,%1,%2,%3};" \
        : "+f"((acc)[0]), "+f"((acc)[1]), "+f"((acc)[2]), "+f"((acc)[3]) \
        : "r"(a0), "r"(a1), "r"(a2), "r"(a3), "r"(b0), "r"(b1))

#define LDMATRIX_X4(r0, r1, r2, r3, addr) \
    asm volatile("ldmatrix.sync.aligned.m8n8.x4.shared.b16 {%0,%1,%2,%3}, [%4];" \
        : "=r"(r0), "=r"(r1), "=r"(r2), "=r"(r3) : "r"(addr))

#define LDMATRIX_X4_TRANS(r0, r1, r2, r3, addr) \
    asm volatile("ldmatrix.sync.aligned.m8n8.x4.trans.shared.b16 {%0,%1,%2,%3}, [%4];" \
        : "=r"(r0), "=r"(r1), "=r"(r2), "=r"(r3) : "r"(addr))

__device__ __forceinline__ uint32_t smem_u32p(const void* p) {
    return (uint32_t)__cvta_generic_to_shared(p);
}

// accurate sincos (immune to --use_fast_math)
__device__ __forceinline__ void rope_sincos(float ang, float& s, float& c) {
    double a  = (double)ang;
    double qd = floor(a * 0.63661977236758134 + 0.5);
    double r  = a - qd * 1.5707963267948966;
    float rf = (float)r;
    int qi = ((int)qd) & 3;
    float r2 = rf * rf;
    float sp = rf * (1.0f + r2 * (-1.6666667e-1f + r2 * (8.3333337e-3f
              + r2 * (-1.9841270e-4f + r2 * 2.7557319e-6f))));
    float cp = 1.0f + r2 * (-0.5f + r2 * (4.1666668e-2f
              + r2 * (-1.3888889e-3f + r2 * 2.4801587e-5f)));
    switch (qi) {
        case 0:  s =  sp; c =  cp; break;
        case 1:  s =  cp; c = -sp; break;
        case 2:  s = -sp; c = -cp; break;
        default: s = -cp; c =  sp; break;
    }
}

// ---------------- fp16 conversion pre-passes ----------------
__global__ void f32_to_f16_kernel(const float2* __restrict__ in, __half2* __restrict__ out, int n2) {
    int i = blockIdx.x * blockDim.x + threadIdx.x;
    if (i < n2) out[i] = __float22half2_rn(in[i]);
}

__global__ void transpose_f16(const float* __restrict__ W, __half* __restrict__ WT,
                              int K, int Nn) {
    __shared__ float t[32][33];
    int n0 = blockIdx.x * 32, k0 = blockIdx.y * 32;
    int tx = threadIdx.x, ty = threadIdx.y;
#pragma unroll
    for (int i = 0; i < 32; i += 8)
        t[ty + i][tx] = W[(size_t)(k0 + ty + i) * Nn + n0 + tx];
    __syncthreads();
#pragma unroll
    for (int i = 0; i < 32; i += 8)
        WT[(size_t)(n0 + ty + i) * K + k0 + tx] = __float2half(t[tx][ty + i]);
}

// ---------------- fp16 tensor-core GEMM with ldmatrix fragment loads ----------------
#define STAGE_B 20480      // bytes per stage: A 10240 + B 10240 (pitch 80 B)
__global__ __launch_bounds__(256) void gemm_f16(
        const __half* __restrict__ A, const __half* __restrict__ BT,
        float* __restrict__ C, int M, int Nn, int K) {
    extern __shared__ char smc[];
    const int tid = threadIdx.x;
    const int bx = blockIdx.x, by = blockIdx.y;
    const int warp = tid >> 5, lane = tid & 31;
    const int gid = lane >> 2, tig = lane & 3;
    const int g = lane >> 3, rr = lane & 7;
    const int warpM = warp & 1, warpN = warp >> 1;
    const int mBase = warpM * 64;
    const int nBase = warpN * 32;

    const __half* Ab = A  + (size_t)(by * 128) * K;
    const __half* Bb = BT + (size_t)(bx * 128) * K;
    const uint32_t smbase = smem_u32p(smc);

    float acc[4][4][4];
#pragma unroll
    for (int mi = 0; mi < 4; mi++)
#pragma unroll
        for (int nj = 0; nj < 4; nj++)
#pragma unroll
            for (int r = 0; r < 4; r++) acc[mi][nj][r] = 0.0f;

    const int KT = K >> 5;

    auto load_tile = [&](int kt, char* buf) {
        char* As = buf;
        char* Bs = buf + 10240;
        int k0 = kt * 32;
#pragma unroll
        for (int i = 0; i < 2; i++) {
            int c = i * 256 + tid;
            int m = c >> 2, k8 = (c & 3) * 8;
            cpasync16(As + m * 80 + k8 * 2, Ab + (size_t)m * K + k0 + k8);
        }
#pragma unroll
        for (int i = 0; i < 2; i++) {
            int c = i * 256 + tid;
            int n = c >> 2, k8 = (c & 3) * 8;
            cpasync16(Bs + n * 80 + k8 * 2, Bb + (size_t)n * K + k0 + k8);
        }
    };

    load_tile(0, smc);
    CP_COMMIT();
    load_tile(1, smc + STAGE_B);
    CP_COMMIT();

    // lane-invariant ldmatrix address components
    const uint32_t aRow = (uint32_t)((mBase + (g & 1) * 8 + rr) * 80) + (uint32_t)((g >> 1) * 16);
    const uint32_t bRow = (uint32_t)((nBase + (g >> 1) * 8 + rr) * 80) + (uint32_t)((g & 1) * 16);

    for (int kt = 0; kt < KT; kt++) {
        CP_WAIT1();
        __syncthreads();
        if (kt + 2 < KT) load_tile(kt + 2, smc + ((kt + 2) % 3) * STAGE_B);
        CP_COMMIT();

        uint32_t ab = smbase + (uint32_t)((kt % 3) * STAGE_B);
        uint32_t bb = ab + 10240;

#pragma unroll
        for (int s = 0; s < 2; s++) {
            uint32_t af[4][4];
            uint32_t bq[2][4];
            uint32_t aoff = ab + aRow + s * 32;
            uint32_t boff = bb + bRow + s * 32;
#pragma unroll
            for (int mi = 0; mi < 4; mi++)
                LDMATRIX_X4(af[mi][0], af[mi][1], af[mi][2], af[mi][3], aoff + mi * (16 * 80));
#pragma unroll
            for (int p = 0; p < 2; p++)
                LDMATRIX_X4(bq[p][0], bq[p][1], bq[p][2], bq[p][3], boff + p * (16 * 80));
#pragma unroll
            for (int mi = 0; mi < 4; mi++)
#pragma unroll
                for (int nj = 0; nj < 4; nj++)
                    MMA_F16(acc[mi][nj], af[mi][0], af[mi][1], af[mi][2], af[mi][3],
                            bq[nj >> 1][(nj & 1) * 2], bq[nj >> 1][(nj & 1) * 2 + 1]);
        }
        __syncthreads();
    }

#pragma unroll
    for (int mi = 0; mi < 4; mi++) {
        int row = by * 128 + mBase + mi * 16 + gid;
#pragma unroll
        for (int nj = 0; nj < 4; nj++) {
            int col = bx * 128 + nBase + nj * 8 + tig * 2;
            *(float2*)(C + (size_t)row * Nn + col)       = make_float2(acc[mi][nj][0], acc[mi][nj][1]);
            *(float2*)(C + (size_t)(row + 8) * Nn + col) = make_float2(acc[mi][nj][2], acc[mi][nj][3]);
        }
    }
}

// ---------------- featurize: RoPE + elu(x*s)+1, outputs fp16 [bh][n][64] ----------------
__global__ void featurize_kernel(const float* __restrict__ qkv,
                                 __half* __restrict__ qh, __half* __restrict__ kh,
                                 __half* __restrict__ vh) {
    int idx = blockIdx.x * blockDim.x + threadIdx.x;
    int d = idx & 31;
    int h = (idx >> 5) & 15;
    int n = (idx >> 9) & 4095;
    int b = idx >> 21;

    size_t base = ((size_t)(b * SEQ + n)) * (3 * DIM);
    int col = h * 64 + d;
    float q1 = qkv[base + col],            q2 = qkv[base + col + 32];
    float k1 = qkv[base + DIM + col],      k2 = qkv[base + DIM + col + 32];
    float v1 = qkv[base + 2 * DIM + col],  v2 = qkv[base + 2 * DIM + col + 32];

    float inv_f = (float)exp(-(double)d * (9.210340371976184 / 32.0));
    float ang = (float)n * inv_f;
    float s, c;
    rope_sincos(ang, s, c);

    float qr1 = q1 * c - q2 * s, qr2 = q1 * s + q2 * c;
    float kr1 = k1 * c - k2 * s, kr2 = k1 * s + k2 * c;

    float yq1 = qr1 * FEAT_SCALE, yq2 = qr2 * FEAT_SCALE;
    float yk1 = kr1 * FEAT_SCALE, yk2 = kr2 * FEAT_SCALE;
    float fq1 = (yq1 > 0.0f) ? yq1 + 1.0f : expf(yq1);
    float fq2 = (yq2 > 0.0f) ? yq2 + 1.0f : expf(yq2);
    float fk1 = (yk1 > 0.0f) ? yk1 + 1.0f : expf(yk1);
    float fk2 = (yk2 > 0.0f) ? yk2 + 1.0f : expf(yk2);

    size_t obase = (((size_t)(b * HEADS + h)) * SEQ + n) * DH + d;
    qh[obase] = __float2half(fq1); qh[obase + 32] = __float2half(fq2);
    kh[obase] = __float2half(fk1); kh[obase + 32] = __float2half(fk2);
    vh[obase] = __float2half(v1);  vh[obase + 32] = __float2half(v2);
}

// ---------------- pass A: per-chunk K^T V (64x64) and sum(k), fp16 in / fp32 out ----------------
__global__ void chunk_sums_kernel(const __half* __restrict__ kh, const __half* __restrict__ vh,
                                  float* __restrict__ kvch, float* __restrict__ ksch) {
    extern __shared__ float sm[];
    float* Ks = sm;
    float* Vs = sm + 8192;

    int blk = blockIdx.x;
    int c  = blk % NCHUNK;
    int bh = blk / NCHUNK;
    int tid = threadIdx.x;

    size_t gbase = (((size_t)bh) * SEQ + (size_t)c * CHUNK) * DH;
    for (int i = tid; i < 1024; i += 256) {
        float4 kraw = ((const float4*)(kh + gbase))[i];
        float4 vraw = ((const float4*)(vh + gbase))[i];
        const __half2* kp = (const __half2*)&kraw;
        const __half2* vp = (const __half2*)&vraw;
#pragma unroll
        for (int j = 0; j < 4; j++) {
            float2 kf2 = __half22float2(kp[j]);
            float2 vf2 = __half22float2(vp[j]);
            Ks[i * 8 + j * 2]     = kf2.x;  Ks[i * 8 + j * 2 + 1] = kf2.y;
            Vs[i * 8 + j * 2]     = vf2.x;  Vs[i * 8 + j * 2 + 1] = vf2.y;
        }
    }
    __syncthreads();

    int i0 = (tid >> 4) * 4;
    int j0 = (tid & 15) * 4;
    float acc[4][4];
#pragma unroll
    for (int i = 0; i < 4; i++)
#pragma unroll
        for (int j = 0; j < 4; j++) acc[i][j] = 0.0f;

    for (int r = 0; r < CHUNK; r++) {
        float4 kv = *(const float4*)&Ks[r * 64 + i0];
        float4 vv = *(const float4*)&Vs[r * 64 + j0];
        float ka[4] = {kv.x, kv.y, kv.z, kv.w};
        float va[4] = {vv.x, vv.y, vv.z, vv.w};
#pragma unroll
        for (int i = 0; i < 4; i++)
#pragma unroll
            for (int j = 0; j < 4; j++) acc[i][j] += ka[i] * va[j];
    }

    size_t obase = ((size_t)bh * NCHUNK + c) * (DH * DH);
#pragma unroll
    for (int i = 0; i < 4; i++)
        *(float4*)&kvch[obase + (size_t)(i0 + i) * 64 + j0] =
            make_float4(acc[i][0], acc[i][1], acc[i][2], acc[i][3]);

    if (tid < 64) {
        float ssum = 0.0f;
        for (int r = 0; r < CHUNK; r++) ssum += Ks[r * 64 + tid];
        ksch[((size_t)bh * NCHUNK + c) * DH + tid] = ssum;
    }
}

// ---------------- pass B: exclusive prefix over chunks (in place) ----------------
__global__ void prefix_kernel(float* __restrict__ kvch, float* __restrict__ ksch) {
    int bh = blockIdx.x;
    for (int e = threadIdx.x; e < DH * DH; e += blockDim.x) {
        float acc = 0.0f;
        for (int c = 0; c < NCHUNK; c++) {
            float* p = &kvch[((size_t)bh * NCHUNK + c) * (DH * DH) + e];
            float t = *p; *p = acc; acc += t;
        }
    }
    for (int e = threadIdx.x; e < DH; e += blockDim.x) {
        float acc = 0.0f;
        for (int c = 0; c < NCHUNK; c++) {
            float* p = &ksch[((size_t)bh * NCHUNK + c) * DH + e];
            float t = *p; *p = acc; acc += t;
        }
    }
}

// ---------------- pass C: tensor-core per-chunk output (ldmatrix fragments) ----------------
#define PQU 36    // u32 pitch for Q/K/V/KVp (144 B rows)
#define PSU 68    // u32 pitch for S (272 B rows)
__global__ __launch_bounds__(256) void chunk_out_tc(
        const __half* __restrict__ qh, const __half* __restrict__ kh,
        const __half* __restrict__ vh, const float* __restrict__ kvch,
        const float* __restrict__ ksch, __half* __restrict__ attn) {
    extern __shared__ char smem[];
    __half* Qh   = (__half*)smem;                    // 128*144 = 18432 B
    __half* Kh   = (__half*)(smem + 18432);          // 18432 B
    __half* Vh   = (__half*)(smem + 36864);          // 18432 B
    __half* KVph = (__half*)(smem + 55296);          // 64*144 = 9216 B
    __half* Sh   = (__half*)(smem + 64512);          // 128*272 = 34816 B
    float* rowsum = (float*)(smem + 99328);          // 512 B
    float* den    = (float*)(smem + 99840);          // 512 B
    float* KSp    = (float*)(smem + 100352);         // 256 B

    const int blk = blockIdx.x;
    const int c  = blk % NCHUNK;
    const int bh = blk / NCHUNK;
    const int b  = bh / HEADS;
    const int h  = bh % HEADS;
    const int tid = threadIdx.x;
    const int warp = tid >> 5, lane = tid & 31;
    const int gid = lane >> 2, tig = lane & 3;
    const int g = lane >> 3, rr = lane & 7;

    // ---- load Q/K/V chunks (fp16, [128][64] -> pitch-144B smem) ----
    size_t gbase = (((size_t)bh) * SEQ + (size_t)c * CHUNK) * DH;
    for (int i = tid; i < 1024; i += 256) {
        int row = i >> 3, c16 = (i & 7) * 16;
        *(float4*)((char*)Qh + row * 144 + c16) = ((const float4*)(qh + gbase))[i];
        *(float4*)((char*)Kh + row * 144 + c16) = ((const float4*)(kh + gbase))[i];
        *(float4*)((char*)Vh + row * 144 + c16) = ((const float4*)(vh + gbase))[i];
    }
    // KVp fp32 -> fp16 smem [64][pitch144]
    {
        size_t kvbase = ((size_t)bh * NCHUNK + c) * (DH * DH);
        for (int i = tid; i < 2048; i += 256) {
            int d = i >> 5, m2 = i & 31;
            float2 f = ((const float2*)(kvch + kvbase))[i];
            *(uint32_t*)((char*)KVph + d * 144 + m2 * 4) =
                h2_to_u32(__floats2half2_rn(f.x, f.y));
        }
        if (tid < 64)
            KSp[tid] = ksch[((size_t)bh * NCHUNK + c) * DH + tid];
    }
    __syncthreads();

    const uint32_t* Qu = (const uint32_t*)Qh;
    uint32_t* Su = (uint32_t*)Sh;
    const uint32_t qbase = smem_u32p(Qh);
    const uint32_t kbase = smem_u32p(Kh);
    const uint32_t sbase = smem_u32p(Sh);
    const int r0 = warp * 16;

    // ldmatrix address components
    const uint32_t aRowQ = (uint32_t)((r0 + (g & 1) * 8 + rr) * 144 + (g >> 1) * 16);
    const uint32_t aRowS = (uint32_t)((r0 + (g & 1) * 8 + rr) * 272 + (g >> 1) * 16);
    const uint32_t bRowK = (uint32_t)(((g >> 1) * 8 + rr) * 144 + (g & 1) * 16);

    // ---- stage 1: S = Q K^T, mask, rowsum, store fp16 ----
    {
        float acc1[16][4];
#pragma unroll
        for (int nt = 0; nt < 16; nt++)
#pragma unroll
            for (int r = 0; r < 4; r++) acc1[nt][r] = 0.0f;

#pragma unroll
        for (int ks = 0; ks < 4; ks++) {
            uint32_t aq[4];
            LDMATRIX_X4(aq[0], aq[1], aq[2], aq[3], qbase + aRowQ + ks * 32);
#pragma unroll
            for (int p = 0; p < 8; p++) {
                uint32_t bk[4];
                LDMATRIX_X4(bk[0], bk[1], bk[2], bk[3],
                            kbase + bRowK + (uint32_t)(p * 16 * 144) + ks * 32);
                MMA_F16(acc1[2 * p],     aq[0], aq[1], aq[2], aq[3], bk[0], bk[1]);
                MMA_F16(acc1[2 * p + 1], aq[0], aq[1], aq[2], aq[3], bk[2], bk[3]);
            }
        }

        int row_lo = r0 + gid, row_hi = row_lo + 8;
        float sum_lo = 0.0f, sum_hi = 0.0f;
#pragma unroll
        for (int nt = 0; nt < 16; nt++) {
            int c0 = nt * 8 + tig * 2, c1 = c0 + 1;
            float v0 = (c0 <= row_lo) ? acc1[nt][0] : 0.0f;
            float v1 = (c1 <= row_lo) ? acc1[nt][1] : 0.0f;
            float v2 = (c0 <= row_hi) ? acc1[nt][2] : 0.0f;
            float v3 = (c1 <= row_hi) ? acc1[nt][3] : 0.0f;
            sum_lo += v0 + v1;
            sum_hi += v2 + v3;
            Su[row_lo * PSU + nt * 4 + tig] = h2_to_u32(__floats2half2_rn(v0, v1));
            Su[row_hi * PSU + nt * 4 + tig] = h2_to_u32(__floats2half2_rn(v2, v3));
        }
        sum_lo += __shfl_xor_sync(0xffffffff, sum_lo, 1);
        sum_lo += __shfl_xor_sync(0xffffffff, sum_lo, 2);
        sum_hi += __shfl_xor_sync(0xffffffff, sum_hi, 1);
        sum_hi += __shfl_xor_sync(0xffffffff, sum_hi, 2);
        if (tig == 0) { rowsum[row_lo] = sum_lo; rowsum[row_hi] = sum_hi; }
    }
    __syncthreads();

    // ---- stage 2: denominators (fp32) ----
    if (tid < 128) {
        float dsum = rowsum[tid];
        const uint32_t* Qr = Qu + tid * PQU;
#pragma unroll
        for (int dd = 0; dd < 32; dd++) {
            float2 qv = __half22float2(u32_to_h2(Qr[dd]));
            dsum += qv.x * KSp[dd * 2] + qv.y * KSp[dd * 2 + 1];
        }
        den[tid] = 1.0f / fmaxf(dsum, 1e-6f);
    }
    __syncthreads();

    // ---- stage 3: O = S_h V + Q KVp ----
    {
        float acc2[8][4];
#pragma unroll
        for (int nt = 0; nt < 8; nt++)
#pragma unroll
            for (int r = 0; r < 4; r++) acc2[nt][r] = 0.0f;

        const uint32_t vbase = smem_u32p(Vh);
        const uint32_t kvbase = smem_u32p(KVph);
        const int sel = lane >> 3;
        const int srow_in = ((sel & 1) << 3) + (lane & 7);
        const int ncol_in = (sel >> 1) << 3;

        // S @ V : contraction over s (128)
#pragma unroll
        for (int ks = 0; ks < 8; ks++) {
            uint32_t as[4];
            LDMATRIX_X4(as[0], as[1], as[2], as[3], sbase + aRowS + ks * 32);
#pragma unroll
            for (int nt2 = 0; nt2 < 4; nt2++) {
                uint32_t addr = vbase + (uint32_t)((ks * 16 + srow_in) * 144 + (nt2 * 16 + ncol_in) * 2);
                uint32_t b0, b1, b2, b3;
                LDMATRIX_X4_TRANS(b0, b1, b2, b3, addr);
                MMA_F16(acc2[nt2 * 2],     as[0], as[1], as[2], as[3], b0, b1);
                MMA_F16(acc2[nt2 * 2 + 1], as[0], as[1], as[2], as[3], b2, b3);
            }
        }
        // Q @ KVp : contraction over d (64)
#pragma unroll
        for (int ks = 0; ks < 4; ks++) {
            uint32_t aq[4];
            LDMATRIX_X4(aq[0], aq[1], aq[2], aq[3], qbase + aRowQ + ks * 32);
#pragma unroll
            for (int nt2 = 0; nt2 < 4; nt2++) {
                uint32_t addr = kvbase + (uint32_t)((ks * 16 + srow_in) * 144 + (nt2 * 16 + ncol_in) * 2);
                uint32_t b0, b1, b2, b3;
                LDMATRIX_X4_TRANS(b0, b1, b2, b3, addr);
                MMA_F16(acc2[nt2 * 2],     aq[0], aq[1], aq[2], aq[3], b0, b1);
                MMA_F16(acc2[nt2 * 2 + 1], aq[0], aq[1], aq[2], aq[3], b2, b3);
            }
        }

        // epilogue: divide by denom, store fp16
        int row_lo = r0 + gid, row_hi = row_lo + 8;
        float inv_lo = den[row_lo], inv_hi = den[row_hi];
        size_t obL = ((size_t)b * SEQ + (size_t)c * CHUNK + row_lo) * DIM + h * 64;
        size_t obH = obL + (size_t)8 * DIM;
#pragma unroll
        for (int nt = 0; nt < 8; nt++) {
            int c0 = nt * 8 + tig * 2;
            *(__half2*)(attn + obL + c0) = __floats2half2_rn(acc2[nt][0] * inv_lo, acc2[nt][1] * inv_lo);
            *(__half2*)(attn + obH + c0) = __floats2half2_rn(acc2[nt][2] * inv_hi, acc2[nt][3] * inv_hi);
        }
    }
}

// ---------------- host launch ----------------
extern "C" void kernel_launch(void* const* d_in, const int* in_sizes, int n_in,
                              void* d_out, int out_size) {
    const float* x    = (const float*)d_in[0];
    const float* wqkv = (const float*)d_in[1];
    const float* wout = (const float*)d_in[2];
    float* out = (float*)d_out;

    float *qkv, *kvch, *ksch;
    __half *xh, *wqkvT, *woutT, *qh, *kh, *vh, *attnh;
    cudaGetSymbolAddress((void**)&qkv,   g_qkv);
    cudaGetSymbolAddress((void**)&xh,    g_xh);
    cudaGetSymbolAddress((void**)&wqkvT, g_wqkvT);
    cudaGetSymbolAddress((void**)&woutT, g_woutT);
    cudaGetSymbolAddress((void**)&qh,    g_qh);
    cudaGetSymbolAddress((void**)&kh,    g_kh);
    cudaGetSymbolAddress((void**)&vh,    g_vh);
    cudaGetSymbolAddress((void**)&attnh, g_attnh);
    cudaGetSymbolAddress((void**)&kvch,  g_kvch);
    cudaGetSymbolAddress((void**)&ksch,  g_ksch);

    const size_t smemG = 3 * STAGE_B;            // 61440 B
    const size_t smemA = 2 * 8192 * sizeof(float);
    const size_t smemC = 100608;
    cudaFuncSetAttribute(gemm_f16,          cudaFuncAttributeMaxDynamicSharedMemorySize, (int)smemG);
    cudaFuncSetAttribute(chunk_sums_kernel, cudaFuncAttributeMaxDynamicSharedMemorySize, (int)smemA);
    cudaFuncSetAttribute(chunk_out_tc,      cudaFuncAttributeMaxDynamicSharedMemorySize, (int)smemC);

    // 0) fp16 conversions
    {
        int n2x = (BATCH * SEQ * DIM) / 2;
        f32_to_f16_kernel<<<(n2x + 255) / 256, 256>>>((const float2*)x, (__half2*)xh, n2x);
        transpose_f16<<<dim3(3 * DIM / 32, DIM / 32), dim3(32, 8)>>>(wqkv, wqkvT, DIM, 3 * DIM);
        transpose_f16<<<dim3(DIM / 32, DIM / 32), dim3(32, 8)>>>(wout, woutT, DIM, DIM);
    }

    // 1) qkv = xh @ wqkvT^T
    gemm_f16<<<dim3(3072 / 128, 16384 / 128), 256, smemG>>>(xh, wqkvT, qkv, BATCH * SEQ, 3 * DIM, DIM);
    // 2) RoPE + elu feature -> fp16 [bh][n][64]
    featurize_kernel<<<(BATCH * SEQ * HEADS * 32) / 256, 256>>>(qkv, qh, kh, vh);
    // 3) per-chunk K^T V sums (fp32 out)
    chunk_sums_kernel<<<BH * NCHUNK, 256, smemA>>>(kh, vh, kvch, ksch);
    // 4) exclusive prefix across chunks
    prefix_kernel<<<BH, 1024>>>(kvch, ksch);
    // 5) per-chunk outputs via tensor cores
    chunk_out_tc<<<BH * NCHUNK, 256, smemC>>>(qh, kh, vh, kvch, ksch, attnh);
    // 6) final = attnh @ woutT^T
    gemm_f16<<<dim3(1024 / 128, 16384 / 128), 256, smemG>>>(attnh, woutT, out, BATCH * SEQ, DIM, DIM);
}

// round 10
// speedup vs baseline: 2.7738x; 1.5623x over previous
#include <cuda_runtime.h>
#include <cuda_fp16.h>
#include <math.h>
#include <stdint.h>

#define BATCH 4
#define SEQ   4096
#define DIM   1024
#define HEADS 16
#define DH    64
#define CHUNK 128
#define NCHUNK 32
#define BH    (BATCH*HEADS)
#define FEAT_SCALE 0.35355339059327373f  // 64^-0.25

// ---------------- scratch (device globals; no allocation allowed) ----------------
__device__ __half g_xh   [BATCH*SEQ*DIM];     // fp16 x
__device__ __half g_wqkvT[3*DIM*DIM];         // K-major fp16
__device__ __half g_woutT[DIM*DIM];           // K-major fp16
__device__ __half g_qh  [BH*SEQ*DH];          // featurized q (fp16)
__device__ __half g_kh  [BH*SEQ*DH];          // featurized k (fp16)
__device__ __half g_vh  [BH*SEQ*DH];          // v (fp16)
__device__ __half g_attnh[BATCH*SEQ*DIM];     // attention out, fp16
__device__ float  g_kvch[BH*NCHUNK*DH*DH];
__device__ float  g_ksch[BH*NCHUNK*DH];

// ---------------- helpers ----------------
__device__ __forceinline__ uint32_t h2_to_u32(__half2 h) {
    __half2_raw r = *(__half2_raw*)&h;
    return (uint32_t)r.x | ((uint32_t)r.y << 16);
}
__device__ __forceinline__ __half2 u32_to_h2(uint32_t u) {
    __half2_raw r;
    r.x = (unsigned short)(u & 0xFFFF);
    r.y = (unsigned short)(u >> 16);
    return *(__half2*)&r;
}
__device__ __forceinline__ void cpasync16(void* dst, const void* src) {
    unsigned d = (unsigned)__cvta_generic_to_shared(dst);
    asm volatile("cp.async.ca.shared.global [%0], [%1], 16;" :: "r"(d), "l"(src));
}
#define CP_COMMIT()  asm volatile("cp.async.commit_group;")
#define CP_WAIT1()   asm volatile("cp.async.wait_group 1;")

#define MMA_F16(acc, a0, a1, a2, a3, b0, b1) \
    asm volatile("mma.sync.aligned.m16n8k16.row.col.f32.f16.f16.f32 " \
        "{%0,%1,%2,%3}, {%4,%5,%6,%7}, {%8,%9}, {%0,%1,%2,%3};" \
        : "+f"((acc)[0]), "+f"((acc)[1]), "+f"((acc)[2]), "+f"((acc)[3]) \
        : "r"(a0), "r"(a1), "r"(a2), "r"(a3), "r"(b0), "r"(b1))

#define LDMATRIX_X4(r0, r1, r2, r3, addr) \
    asm volatile("ldmatrix.sync.aligned.m8n8.x4.shared.b16 {%0,%1,%2,%3}, [%4];" \
        : "=r"(r0), "=r"(r1), "=r"(r2), "=r"(r3) : "r"(addr))

#define LDMATRIX_X4_TRANS(r0, r1, r2, r3, addr) \
    asm volatile("ldmatrix.sync.aligned.m8n8.x4.trans.shared.b16 {%0,%1,%2,%3}, [%4];" \
        : "=r"(r0), "=r"(r1), "=r"(r2), "=r"(r3) : "r"(addr))

__device__ __forceinline__ uint32_t smem_u32p(const void* p) {
    return (uint32_t)__cvta_generic_to_shared(p);
}

// fp32 sincos, FMA Cody-Waite range reduction (accurate to ~1e-7 for ang < 5000;
// immune to --use_fast_math).
__device__ __forceinline__ void rope_sincos_f(float ang, float& s, float& c) {
    float qf = rintf(ang * 0.63661977f);
    float r = fmaf(-qf, 1.57079637e+0f, ang);   // pi/2 hi (0x3FC90FDB)
    r = fmaf(qf, 4.37113900e-8f, r);            // pi/2 = HI - 4.371139e-8
    int qi = (int)qf & 3;
    float r2 = r * r;
    float sp = r * (1.0f + r2 * (-1.6666667e-1f + r2 * (8.3333337e-3f
              + r2 * (-1.9841270e-4f + r2 * 2.7557319e-6f))));
    float cp = 1.0f + r2 * (-0.5f + r2 * (4.1666668e-2f
              + r2 * (-1.3888889e-3f + r2 * 2.4801587e-5f)));
    switch (qi) {
        case 0:  s =  sp; c =  cp; break;
        case 1:  s =  cp; c = -sp; break;
        case 2:  s = -sp; c = -cp; break;
        default: s = -cp; c =  sp; break;
    }
}

// ---------------- fp16 conversion pre-passes ----------------
__global__ void f32_to_f16_kernel(const float2* __restrict__ in, __half2* __restrict__ out, int n2) {
    int i = blockIdx.x * blockDim.x + threadIdx.x;
    if (i < n2) out[i] = __float22half2_rn(in[i]);
}

__global__ void transpose_f16(const float* __restrict__ W, __half* __restrict__ WT,
                              int K, int Nn) {
    __shared__ float t[32][33];
    int n0 = blockIdx.x * 32, k0 = blockIdx.y * 32;
    int tx = threadIdx.x, ty = threadIdx.y;
#pragma unroll
    for (int i = 0; i < 32; i += 8)
        t[ty + i][tx] = W[(size_t)(k0 + ty + i) * Nn + n0 + tx];
    __syncthreads();
#pragma unroll
    for (int i = 0; i < 32; i += 8)
        WT[(size_t)(n0 + ty + i) * K + k0 + tx] = __float2half(t[tx][ty + i]);
}

// ---------------- generic fp16 GEMM (for output projection) ----------------
#define STAGE_B 20480      // bytes per stage: A 10240 + B 10240 (pitch 80 B)
__global__ __launch_bounds__(256) void gemm_f16(
        const __half* __restrict__ A, const __half* __restrict__ BT,
        float* __restrict__ C, int M, int Nn, int K) {
    extern __shared__ char smc[];
    const int tid = threadIdx.x;
    const int bx = blockIdx.x, by = blockIdx.y;
    const int warp = tid >> 5, lane = tid & 31;
    const int gid = lane >> 2, tig = lane & 3;
    const int g = lane >> 3, rr = lane & 7;
    const int warpM = warp & 1, warpN = warp >> 1;
    const int mBase = warpM * 64;
    const int nBase = warpN * 32;

    const __half* Ab = A  + (size_t)(by * 128) * K;
    const __half* Bb = BT + (size_t)(bx * 128) * K;
    const uint32_t smbase = smem_u32p(smc);

    float acc[4][4][4];
#pragma unroll
    for (int mi = 0; mi < 4; mi++)
#pragma unroll
        for (int nj = 0; nj < 4; nj++)
#pragma unroll
            for (int r = 0; r < 4; r++) acc[mi][nj][r] = 0.0f;

    const int KT = K >> 5;

    auto load_tile = [&](int kt, char* buf) {
        char* As = buf;
        char* Bs = buf + 10240;
        int k0 = kt * 32;
#pragma unroll
        for (int i = 0; i < 2; i++) {
            int c = i * 256 + tid;
            int m = c >> 2, k8 = (c & 3) * 8;
            cpasync16(As + m * 80 + k8 * 2, Ab + (size_t)m * K + k0 + k8);
        }
#pragma unroll
        for (int i = 0; i < 2; i++) {
            int c = i * 256 + tid;
            int n = c >> 2, k8 = (c & 3) * 8;
            cpasync16(Bs + n * 80 + k8 * 2, Bb + (size_t)n * K + k0 + k8);
        }
    };

    load_tile(0, smc);
    CP_COMMIT();
    load_tile(1, smc + STAGE_B);
    CP_COMMIT();

    const uint32_t aRow = (uint32_t)((mBase + (g & 1) * 8 + rr) * 80) + (uint32_t)((g >> 1) * 16);
    const uint32_t bRow = (uint32_t)((nBase + (g >> 1) * 8 + rr) * 80) + (uint32_t)((g & 1) * 16);

    for (int kt = 0; kt < KT; kt++) {
        CP_WAIT1();
        __syncthreads();
        if (kt + 2 < KT) load_tile(kt + 2, smc + ((kt + 2) % 3) * STAGE_B);
        CP_COMMIT();

        uint32_t ab = smbase + (uint32_t)((kt % 3) * STAGE_B);
        uint32_t bb = ab + 10240;

#pragma unroll
        for (int s = 0; s < 2; s++) {
            uint32_t af[4][4];
            uint32_t bq[2][4];
            uint32_t aoff = ab + aRow + s * 32;
            uint32_t boff = bb + bRow + s * 32;
#pragma unroll
            for (int mi = 0; mi < 4; mi++)
                LDMATRIX_X4(af[mi][0], af[mi][1], af[mi][2], af[mi][3], aoff + mi * (16 * 80));
#pragma unroll
            for (int p = 0; p < 2; p++)
                LDMATRIX_X4(bq[p][0], bq[p][1], bq[p][2], bq[p][3], boff + p * (16 * 80));
#pragma unroll
            for (int mi = 0; mi < 4; mi++)
#pragma unroll
                for (int nj = 0; nj < 4; nj++)
                    MMA_F16(acc[mi][nj], af[mi][0], af[mi][1], af[mi][2], af[mi][3],
                            bq[nj >> 1][(nj & 1) * 2], bq[nj >> 1][(nj & 1) * 2 + 1]);
        }
        __syncthreads();
    }

#pragma unroll
    for (int mi = 0; mi < 4; mi++) {
        int row = by * 128 + mBase + mi * 16 + gid;
#pragma unroll
        for (int nj = 0; nj < 4; nj++) {
            int col = bx * 128 + nBase + nj * 8 + tig * 2;
            *(float2*)(C + (size_t)row * Nn + col)       = make_float2(acc[mi][nj][0], acc[mi][nj][1]);
            *(float2*)(C + (size_t)(row + 8) * Nn + col) = make_float2(acc[mi][nj][2], acc[mi][nj][3]);
        }
    }
}

// ---------------- fused QKV GEMM + RoPE + ELU featurize ----------------
// Same mainloop as gemm_f16 (Nn=3072, K=1024). Epilogue stages the fp32 tile
// in smem, applies RoPE+ELU (q/k) or passthrough (v), writes fp16 [bh][n][64].
__global__ __launch_bounds__(256) void gemm_qkv(
        const __half* __restrict__ A, const __half* __restrict__ BT,
        __half* __restrict__ qh, __half* __restrict__ kh, __half* __restrict__ vh) {
    extern __shared__ char smc[];
    const int K = DIM;
    const int tid = threadIdx.x;
    const int bx = blockIdx.x, by = blockIdx.y;
    const int warp = tid >> 5, lane = tid & 31;
    const int gid = lane >> 2, tig = lane & 3;
    const int g = lane >> 3, rr = lane & 7;
    const int warpM = warp & 1, warpN = warp >> 1;
    const int mBase = warpM * 64;
    const int nBase = warpN * 32;

    const __half* Ab = A + (size_t)(by * 128) * K;
    const __half* Bb = BT + (size_t)(bx * 128) * K;
    const uint32_t smbase = smem_u32p(smc);

    float acc[4][4][4];
#pragma unroll
    for (int mi = 0; mi < 4; mi++)
#pragma unroll
        for (int nj = 0; nj < 4; nj++)
#pragma unroll
            for (int r = 0; r < 4; r++) acc[mi][nj][r] = 0.0f;

    const int KT = K >> 5;

    auto load_tile = [&](int kt, char* buf) {
        char* As = buf;
        char* Bs = buf + 10240;
        int k0 = kt * 32;
#pragma unroll
        for (int i = 0; i < 2; i++) {
            int c = i * 256 + tid;
            int m = c >> 2, k8 = (c & 3) * 8;
            cpasync16(As + m * 80 + k8 * 2, Ab + (size_t)m * K + k0 + k8);
        }
#pragma unroll
        for (int i = 0; i < 2; i++) {
            int c = i * 256 + tid;
            int n = c >> 2, k8 = (c & 3) * 8;
            cpasync16(Bs + n * 80 + k8 * 2, Bb + (size_t)n * K + k0 + k8);
        }
    };

    load_tile(0, smc);
    CP_COMMIT();
    load_tile(1, smc + STAGE_B);
    CP_COMMIT();

    const uint32_t aRow = (uint32_t)((mBase + (g & 1) * 8 + rr) * 80) + (uint32_t)((g >> 1) * 16);
    const uint32_t bRow = (uint32_t)((nBase + (g >> 1) * 8 + rr) * 80) + (uint32_t)((g & 1) * 16);

    for (int kt = 0; kt < KT; kt++) {
        CP_WAIT1();
        __syncthreads();
        if (kt + 2 < KT) load_tile(kt + 2, smc + ((kt + 2) % 3) * STAGE_B);
        CP_COMMIT();

        uint32_t ab = smbase + (uint32_t)((kt % 3) * STAGE_B);
        uint32_t bb = ab + 10240;

#pragma unroll
        for (int s = 0; s < 2; s++) {
            uint32_t af[4][4];
            uint32_t bq[2][4];
            uint32_t aoff = ab + aRow + s * 32;
            uint32_t boff = bb + bRow + s * 32;
#pragma unroll
            for (int mi = 0; mi < 4; mi++)
                LDMATRIX_X4(af[mi][0], af[mi][1], af[mi][2], af[mi][3], aoff + mi * (16 * 80));
#pragma unroll
            for (int p = 0; p < 2; p++)
                LDMATRIX_X4(bq[p][0], bq[p][1], bq[p][2], bq[p][3], boff + p * (16 * 80));
#pragma unroll
            for (int mi = 0; mi < 4; mi++)
#pragma unroll
                for (int nj = 0; nj < 4; nj++)
                    MMA_F16(acc[mi][nj], af[mi][0], af[mi][1], af[mi][2], af[mi][3],
                            bq[nj >> 1][(nj & 1) * 2], bq[nj >> 1][(nj & 1) * 2 + 1]);
        }
        __syncthreads();
    }

    // ---- epilogue: stage tile fp32, featurize, store fp16 ----
    float* St = (float*)smc;        // 128 x pitch 132 floats = 67584 B
#pragma unroll
    for (int mi = 0; mi < 4; mi++) {
        int r = mBase + mi * 16 + gid;
#pragma unroll
        for (int nj = 0; nj < 4; nj++) {
            int ccol = nBase + nj * 8 + tig * 2;
            *(float2*)&St[r * 132 + ccol]       = make_float2(acc[mi][nj][0], acc[mi][nj][1]);
            *(float2*)&St[(r + 8) * 132 + ccol] = make_float2(acc[mi][nj][2], acc[mi][nj][3]);
        }
    }
    __syncthreads();

    const int sel   = bx >> 3;           // 0=q, 1=k, 2=v
    const int hbase = (bx & 7) * 2;
    const int d     = tid & 31;
    const int hh    = (tid >> 5) & 1;
    const int rbase = tid >> 6;          // 0..3
    const int bb    = by >> 5;           // batch
    const int n0    = (by * 128) & 4095;

    __half* dst = (sel == 0) ? qh : ((sel == 1) ? kh : vh);
    float inv_f = (sel < 2) ? (float)exp(-(double)d * (9.210340371976184 / 32.0)) : 0.0f;

#pragma unroll 4
    for (int k = 0; k < 32; k++) {
        int row = rbase + k * 4;
        float x1 = St[row * 132 + hh * 64 + d];
        float x2 = St[row * 132 + hh * 64 + d + 32];
        float f1, f2;
        if (sel == 2) {
            f1 = x1; f2 = x2;
        } else {
            float ang = (float)(n0 + row) * inv_f;
            float s, c;
            rope_sincos_f(ang, s, c);
            float y1 = (x1 * c - x2 * s) * FEAT_SCALE;
            float y2 = (x1 * s + x2 * c) * FEAT_SCALE;
            f1 = (y1 > 0.0f) ? y1 + 1.0f : expf(y1);
            f2 = (y2 > 0.0f) ? y2 + 1.0f : expf(y2);
        }
        size_t ob = (((size_t)(bb * HEADS + hbase + hh)) * SEQ + (n0 + row)) * DH + d;
        dst[ob]      = __float2half(f1);
        dst[ob + 32] = __float2half(f2);
    }
}

// ---------------- pass A: tensor-core per-chunk K^T V (64x64) and sum(k) ----------------
__global__ __launch_bounds__(256) void chunk_sums_tc(
        const __half* __restrict__ kh, const __half* __restrict__ vh,
        float* __restrict__ kvch, float* __restrict__ ksch) {
    extern __shared__ char smem[];
    __half* Kh = (__half*)smem;              // 128 x 144 B = 18432
    __half* Vh = (__half*)(smem + 18432);    // 18432

    const int blk = blockIdx.x;
    const int c  = blk % NCHUNK;
    const int bh = blk / NCHUNK;
    const int tid = threadIdx.x;
    const int warp = tid >> 5, lane = tid & 31;
    const int gid = lane >> 2, tig = lane & 3;
    const int g = lane >> 3, rr = lane & 7;

    size_t gbase = (((size_t)bh) * SEQ + (size_t)c * CHUNK) * DH;
    for (int i = tid; i < 1024; i += 256) {
        int row = i >> 3, c16 = (i & 7) * 16;
        *(float4*)((char*)Kh + row * 144 + c16) = ((const float4*)(kh + gbase))[i];
        *(float4*)((char*)Vh + row * 144 + c16) = ((const float4*)(vh + gbase))[i];
    }
    __syncthreads();

    const uint32_t kbase = smem_u32p(Kh);
    const uint32_t vbase = smem_u32p(Vh);
    const int d0 = (warp & 3) * 16;          // output rows (K-dim)
    const int m0 = (warp >> 2) * 32;         // output cols (V-dim)

    float acc[4][4];
#pragma unroll
    for (int nt = 0; nt < 4; nt++)
#pragma unroll
        for (int r = 0; r < 4; r++) acc[nt][r] = 0.0f;

    // A = K^T (trans load), B = V^T (trans load)
    const uint32_t aAddr = (uint32_t)(((g >> 1) * 8 + rr) * 144 + (d0 + (g & 1) * 8) * 2);
    const uint32_t bAddr = (uint32_t)(((g & 1) * 8 + rr) * 144 + (m0 + (g >> 1) * 8) * 2);

#pragma unroll
    for (int ks = 0; ks < 8; ks++) {
        uint32_t a0, a1, a2, a3;
        LDMATRIX_X4_TRANS(a0, a1, a2, a3, kbase + aAddr + (uint32_t)(ks * 16 * 144));
#pragma unroll
        for (int p = 0; p < 2; p++) {
            uint32_t b0, b1, b2, b3;
            LDMATRIX_X4_TRANS(b0, b1, b2, b3,
                              vbase + bAddr + (uint32_t)(ks * 16 * 144) + (uint32_t)(p * 32));
            MMA_F16(acc[p * 2],     a0, a1, a2, a3, b0, b1);
            MMA_F16(acc[p * 2 + 1], a0, a1, a2, a3, b2, b3);
        }
    }

    size_t obase = ((size_t)bh * NCHUNK + c) * (DH * DH);
    int row_lo = d0 + gid, row_hi = row_lo + 8;
#pragma unroll
    for (int nt = 0; nt < 4; nt++) {
        int col = m0 + nt * 8 + tig * 2;
        *(float2*)&kvch[obase + (size_t)row_lo * 64 + col] = make_float2(acc[nt][0], acc[nt][1]);
        *(float2*)&kvch[obase + (size_t)row_hi * 64 + col] = make_float2(acc[nt][2], acc[nt][3]);
    }

    if (tid < 64) {
        float ssum = 0.0f;
        for (int r = 0; r < 128; r++)
            ssum += __half2float(Kh[r * 72 + tid]);
        ksch[((size_t)bh * NCHUNK + c) * DH + tid] = ssum;
    }
}

// ---------------- pass B: exclusive prefix over chunks (in place) ----------------
__global__ void prefix_kernel(float* __restrict__ kvch, float* __restrict__ ksch) {
    int bh = blockIdx.x;
    for (int e = threadIdx.x; e < DH * DH; e += blockDim.x) {
        float acc = 0.0f;
        for (int c = 0; c < NCHUNK; c++) {
            float* p = &kvch[((size_t)bh * NCHUNK + c) * (DH * DH) + e];
            float t = *p; *p = acc; acc += t;
        }
    }
    for (int e = threadIdx.x; e < DH; e += blockDim.x) {
        float acc = 0.0f;
        for (int c = 0; c < NCHUNK; c++) {
            float* p = &ksch[((size_t)bh * NCHUNK + c) * DH + e];
            float t = *p; *p = acc; acc += t;
        }
    }
}

// ---------------- pass C: tensor-core per-chunk output (R9, unchanged) ----------------
#define PQU 36    // u32 pitch for Q/K/V/KVp (144 B rows)
#define PSU 68    // u32 pitch for S (272 B rows)
__global__ __launch_bounds__(256) void chunk_out_tc(
        const __half* __restrict__ qh, const __half* __restrict__ kh,
        const __half* __restrict__ vh, const float* __restrict__ kvch,
        const float* __restrict__ ksch, __half* __restrict__ attn) {
    extern __shared__ char smem[];
    __half* Qh   = (__half*)smem;                    // 18432 B
    __half* Kh   = (__half*)(smem + 18432);          // 18432 B
    __half* Vh   = (__half*)(smem + 36864);          // 18432 B
    __half* KVph = (__half*)(smem + 55296);          // 9216 B
    __half* Sh   = (__half*)(smem + 64512);          // 34816 B
    float* rowsum = (float*)(smem + 99328);
    float* den    = (float*)(smem + 99840);
    float* KSp    = (float*)(smem + 100352);

    const int blk = blockIdx.x;
    const int c  = blk % NCHUNK;
    const int bh = blk / NCHUNK;
    const int b  = bh / HEADS;
    const int h  = bh % HEADS;
    const int tid = threadIdx.x;
    const int warp = tid >> 5, lane = tid & 31;
    const int gid = lane >> 2, tig = lane & 3;
    const int g = lane >> 3, rr = lane & 7;

    size_t gbase = (((size_t)bh) * SEQ + (size_t)c * CHUNK) * DH;
    for (int i = tid; i < 1024; i += 256) {
        int row = i >> 3, c16 = (i & 7) * 16;
        *(float4*)((char*)Qh + row * 144 + c16) = ((const float4*)(qh + gbase))[i];
        *(float4*)((char*)Kh + row * 144 + c16) = ((const float4*)(kh + gbase))[i];
        *(float4*)((char*)Vh + row * 144 + c16) = ((const float4*)(vh + gbase))[i];
    }
    {
        size_t kvbase = ((size_t)bh * NCHUNK + c) * (DH * DH);
        for (int i = tid; i < 2048; i += 256) {
            int d = i >> 5, m2 = i & 31;
            float2 f = ((const float2*)(kvch + kvbase))[i];
            *(uint32_t*)((char*)KVph + d * 144 + m2 * 4) =
                h2_to_u32(__floats2half2_rn(f.x, f.y));
        }
        if (tid < 64)
            KSp[tid] = ksch[((size_t)bh * NCHUNK + c) * DH + tid];
    }
    __syncthreads();

    const uint32_t* Qu = (const uint32_t*)Qh;
    uint32_t* Su = (uint32_t*)Sh;
    const uint32_t qbase = smem_u32p(Qh);
    const uint32_t kbase = smem_u32p(Kh);
    const uint32_t sbase = smem_u32p(Sh);
    const int r0 = warp * 16;

    const uint32_t aRowQ = (uint32_t)((r0 + (g & 1) * 8 + rr) * 144 + (g >> 1) * 16);
    const uint32_t aRowS = (uint32_t)((r0 + (g & 1) * 8 + rr) * 272 + (g >> 1) * 16);
    const uint32_t bRowK = (uint32_t)(((g >> 1) * 8 + rr) * 144 + (g & 1) * 16);

    // ---- stage 1: S = Q K^T, mask, rowsum, store fp16 ----
    {
        float acc1[16][4];
#pragma unroll
        for (int nt = 0; nt < 16; nt++)
#pragma unroll
            for (int r = 0; r < 4; r++) acc1[nt][r] = 0.0f;

#pragma unroll
        for (int ks = 0; ks < 4; ks++) {
            uint32_t aq[4];
            LDMATRIX_X4(aq[0], aq[1], aq[2], aq[3], qbase + aRowQ + ks * 32);
#pragma unroll
            for (int p = 0; p < 8; p++) {
                uint32_t bk[4];
                LDMATRIX_X4(bk[0], bk[1], bk[2], bk[3],
                            kbase + bRowK + (uint32_t)(p * 16 * 144) + ks * 32);
                MMA_F16(acc1[2 * p],     aq[0], aq[1], aq[2], aq[3], bk[0], bk[1]);
                MMA_F16(acc1[2 * p + 1], aq[0], aq[1], aq[2], aq[3], bk[2], bk[3]);
            }
        }

        int row_lo = r0 + gid, row_hi = row_lo + 8;
        float sum_lo = 0.0f, sum_hi = 0.0f;
#pragma unroll
        for (int nt = 0; nt < 16; nt++) {
            int c0 = nt * 8 + tig * 2, c1 = c0 + 1;
            float v0 = (c0 <= row_lo) ? acc1[nt][0] : 0.0f;
            float v1 = (c1 <= row_lo) ? acc1[nt][1] : 0.0f;
            float v2 = (c0 <= row_hi) ? acc1[nt][2] : 0.0f;
            float v3 = (c1 <= row_hi) ? acc1[nt][3] : 0.0f;
            sum_lo += v0 + v1;
            sum_hi += v2 + v3;
            Su[row_lo * PSU + nt * 4 + tig] = h2_to_u32(__floats2half2_rn(v0, v1));
            Su[row_hi * PSU + nt * 4 + tig] = h2_to_u32(__floats2half2_rn(v2, v3));
        }
        sum_lo += __shfl_xor_sync(0xffffffff, sum_lo, 1);
        sum_lo += __shfl_xor_sync(0xffffffff, sum_lo, 2);
        sum_hi += __shfl_xor_sync(0xffffffff, sum_hi, 1);
        sum_hi += __shfl_xor_sync(0xffffffff, sum_hi, 2);
        if (tig == 0) { rowsum[row_lo] = sum_lo; rowsum[row_hi] = sum_hi; }
    }
    __syncthreads();

    if (tid < 128) {
        float dsum = rowsum[tid];
        const uint32_t* Qr = Qu + tid * PQU;
#pragma unroll
        for (int dd = 0; dd < 32; dd++) {
            float2 qv = __half22float2(u32_to_h2(Qr[dd]));
            dsum += qv.x * KSp[dd * 2] + qv.y * KSp[dd * 2 + 1];
        }
        den[tid] = 1.0f / fmaxf(dsum, 1e-6f);
    }
    __syncthreads();

    {
        float acc2[8][4];
#pragma unroll
        for (int nt = 0; nt < 8; nt++)
#pragma unroll
            for (int r = 0; r < 4; r++) acc2[nt][r] = 0.0f;

        const uint32_t vbase = smem_u32p(Vh);
        const uint32_t kvbase = smem_u32p(KVph);
        const int sel = lane >> 3;
        const int srow_in = ((sel & 1) << 3) + (lane & 7);
        const int ncol_in = (sel >> 1) << 3;

#pragma unroll
        for (int ks = 0; ks < 8; ks++) {
            uint32_t as[4];
            LDMATRIX_X4(as[0], as[1], as[2], as[3], sbase + aRowS + ks * 32);
#pragma unroll
            for (int nt2 = 0; nt2 < 4; nt2++) {
                uint32_t addr = vbase + (uint32_t)((ks * 16 + srow_in) * 144 + (nt2 * 16 + ncol_in) * 2);
                uint32_t b0, b1, b2, b3;
                LDMATRIX_X4_TRANS(b0, b1, b2, b3, addr);
                MMA_F16(acc2[nt2 * 2],     as[0], as[1], as[2], as[3], b0, b1);
                MMA_F16(acc2[nt2 * 2 + 1], as[0], as[1], as[2], as[3], b2, b3);
            }
        }
#pragma unroll
        for (int ks = 0; ks < 4; ks++) {
            uint32_t aq[4];
            LDMATRIX_X4(aq[0], aq[1], aq[2], aq[3], qbase + aRowQ + ks * 32);
#pragma unroll
            for (int nt2 = 0; nt2 < 4; nt2++) {
                uint32_t addr = kvbase + (uint32_t)((ks * 16 + srow_in) * 144 + (nt2 * 16 + ncol_in) * 2);
                uint32_t b0, b1, b2, b3;
                LDMATRIX_X4_TRANS(b0, b1, b2, b3, addr);
                MMA_F16(acc2[nt2 * 2],     aq[0], aq[1], aq[2], aq[3], b0, b1);
                MMA_F16(acc2[nt2 * 2 + 1], aq[0], aq[1], aq[2], aq[3], b2, b3);
            }
        }

        int row_lo = r0 + gid, row_hi = row_lo + 8;
        float inv_lo = den[row_lo], inv_hi = den[row_hi];
        size_t obL = ((size_t)b * SEQ + (size_t)c * CHUNK + row_lo) * DIM + h * 64;
        size_t obH = obL + (size_t)8 * DIM;
#pragma unroll
        for (int nt = 0; nt < 8; nt++) {
            int c0 = nt * 8 + tig * 2;
            *(__half2*)(attn + obL + c0) = __floats2half2_rn(acc2[nt][0] * inv_lo, acc2[nt][1] * inv_lo);
            *(__half2*)(attn + obH + c0) = __floats2half2_rn(acc2[nt][2] * inv_hi, acc2[nt][3] * inv_hi);
        }
    }
}

// ---------------- host launch ----------------
extern "C" void kernel_launch(void* const* d_in, const int* in_sizes, int n_in,
                              void* d_out, int out_size) {
    const float* x    = (const float*)d_in[0];
    const float* wqkv = (const float*)d_in[1];
    const float* wout = (const float*)d_in[2];
    float* out = (float*)d_out;

    float *kvch, *ksch;
    __half *xh, *wqkvT, *woutT, *qh, *kh, *vh, *attnh;
    cudaGetSymbolAddress((void**)&xh,    g_xh);
    cudaGetSymbolAddress((void**)&wqkvT, g_wqkvT);
    cudaGetSymbolAddress((void**)&woutT, g_woutT);
    cudaGetSymbolAddress((void**)&qh,    g_qh);
    cudaGetSymbolAddress((void**)&kh,    g_kh);
    cudaGetSymbolAddress((void**)&vh,    g_vh);
    cudaGetSymbolAddress((void**)&attnh, g_attnh);
    cudaGetSymbolAddress((void**)&kvch,  g_kvch);
    cudaGetSymbolAddress((void**)&ksch,  g_ksch);

    const size_t smemG  = 3 * STAGE_B;               // 61440 B
    const size_t smemGQ = 128 * 132 * sizeof(float); // 67584 B (>= pipeline smem)
    const size_t smemS  = 2 * 18432;                 // 36864 B
    const size_t smemC  = 100608;
    cudaFuncSetAttribute(gemm_f16,      cudaFuncAttributeMaxDynamicSharedMemorySize, (int)smemG);
    cudaFuncSetAttribute(gemm_qkv,      cudaFuncAttributeMaxDynamicSharedMemorySize, (int)smemGQ);
    cudaFuncSetAttribute(chunk_sums_tc, cudaFuncAttributeMaxDynamicSharedMemorySize, (int)smemS);
    cudaFuncSetAttribute(chunk_out_tc,  cudaFuncAttributeMaxDynamicSharedMemorySize, (int)smemC);

    // 0) fp16 conversions
    {
        int n2x = (BATCH * SEQ * DIM) / 2;
        f32_to_f16_kernel<<<(n2x + 255) / 256, 256>>>((const float2*)x, (__half2*)xh, n2x);
        transpose_f16<<<dim3(3 * DIM / 32, DIM / 32), dim3(32, 8)>>>(wqkv, wqkvT, DIM, 3 * DIM);
        transpose_f16<<<dim3(DIM / 32, DIM / 32), dim3(32, 8)>>>(wout, woutT, DIM, DIM);
    }

    // 1) fused qkv GEMM + RoPE + ELU -> fp16 q/k/v in [bh][n][64]
    gemm_qkv<<<dim3(3072 / 128, 16384 / 128), 256, smemGQ>>>(xh, wqkvT, qh, kh, vh);
    // 2) per-chunk K^T V sums (tensor cores, fp32 out)
    chunk_sums_tc<<<BH * NCHUNK, 256, smemS>>>(kh, vh, kvch, ksch);
    // 3) exclusive prefix across chunks
    prefix_kernel<<<BH, 1024>>>(kvch, ksch);
    // 4) per-chunk outputs via tensor cores
    chunk_out_tc<<<BH * NCHUNK, 256, smemC>>>(qh, kh, vh, kvch, ksch, attnh);
    // 5) final = attnh @ woutT^T
    gemm_f16<<<dim3(1024 / 128, 16384 / 128), 256, smemG>>>(attnh, woutT, out, BATCH * SEQ, DIM, DIM);
}